// round 1
// baseline (speedup 1.0000x reference)
#include <cuda_runtime.h>
#include <cuda_bf16.h>
#include <math.h>

#define BS 2
#define CH 128
#define NN 16
#define WW 32
#define HH 32
#define NS (NN*WW*HH)      /* 16384 query locations per batch */
#define MM (NN*(WW/2)*(HH/2)) /* 4096 pooled key locations per batch */
#define C1 16
#define C2 64
#define NCHUNK 8           /* n-chunks for denom pass */

// ---------------- scratch (device globals; no allocs allowed) ----------------
__device__ float d_theta  [BS*NS*C1];   // (b, s, c1)  tanh(theta proj)
__device__ float d_phifull[BS*NS*C1];   // (b, s, c1)  tanh(phi proj), pre-pool
__device__ float d_gfull  [BS*NS*C2];   // (b, s, c2)  g proj, pre-pool
__device__ float d_phi    [BS*MM*C1];   // (b, m, c1)
__device__ float d_g      [BS*MM*C2];   // (b, m, c2)
__device__ float d_denomp [BS*MM*NCHUNK]; // per-chunk partial denominators
__device__ float d_attng  [BS*NS*C2];   // (b, s, c2)  attn @ g

__device__ __forceinline__ float dot16(float4 a0, float4 a1, float4 a2, float4 a3,
                                       float4 b0, float4 b1, float4 b2, float4 b3) {
    float s0 = a0.x*b0.x; s0 = fmaf(a0.y, b0.y, s0);
    float s1 = a0.z*b0.z; s1 = fmaf(a0.w, b0.w, s1);
    float s2 = a1.x*b1.x; s2 = fmaf(a1.y, b1.y, s2);
    float s3 = a1.z*b1.z; s3 = fmaf(a1.w, b1.w, s3);
    s0 = fmaf(a2.x, b2.x, s0); s0 = fmaf(a2.y, b2.y, s0);
    s1 = fmaf(a2.z, b2.z, s1); s1 = fmaf(a2.w, b2.w, s1);
    s2 = fmaf(a3.x, b3.x, s2); s2 = fmaf(a3.y, b3.y, s2);
    s3 = fmaf(a3.z, b3.z, s3); s3 = fmaf(a3.w, b3.w, s3);
    return (s0 + s1) + (s2 + s3);
}

// ---------------- K1a: theta & phi (full-res) projections + tanh ----------------
__global__ void __launch_bounds__(128)
proj16_kernel(const float* __restrict__ x,
              const float* __restrict__ wth, const float* __restrict__ bth,
              const float* __restrict__ wph, const float* __restrict__ bph) {
    __shared__ float swt[CH*C1];  // [c][o]
    __shared__ float swp[CH*C1];  // [c][o]
    __shared__ float sbt[C1], sbp[C1];
    int tid = threadIdx.x;
    for (int i = tid; i < CH*C1; i += 128) {
        int o = i >> 7, c = i & 127;   // source is [o][c], o<16, c<128
        swt[c*C1 + o] = wth[i];
        swp[c*C1 + o] = wph[i];
    }
    if (tid < C1) { sbt[tid] = bth[tid]; sbp[tid] = bph[tid]; }
    __syncthreads();

    int b = blockIdx.y;
    int s = blockIdx.x * 128 + tid;
    const float* xp = x + (size_t)b*CH*NS + s;

    float4 t4[4], p4[4];
#pragma unroll
    for (int j = 0; j < 4; j++) {
        t4[j] = make_float4(sbt[4*j], sbt[4*j+1], sbt[4*j+2], sbt[4*j+3]);
        p4[j] = make_float4(sbp[4*j], sbp[4*j+1], sbp[4*j+2], sbp[4*j+3]);
    }
#pragma unroll 4
    for (int c = 0; c < CH; c++) {
        float xv = xp[(size_t)c*NS];
        const float4* wt4 = (const float4*)(swt + c*C1);
        const float4* wp4 = (const float4*)(swp + c*C1);
#pragma unroll
        for (int j = 0; j < 4; j++) {
            float4 w = wt4[j];
            t4[j].x = fmaf(xv, w.x, t4[j].x); t4[j].y = fmaf(xv, w.y, t4[j].y);
            t4[j].z = fmaf(xv, w.z, t4[j].z); t4[j].w = fmaf(xv, w.w, t4[j].w);
            float4 v = wp4[j];
            p4[j].x = fmaf(xv, v.x, p4[j].x); p4[j].y = fmaf(xv, v.y, p4[j].y);
            p4[j].z = fmaf(xv, v.z, p4[j].z); p4[j].w = fmaf(xv, v.w, p4[j].w);
        }
    }
    float4* to = (float4*)&d_theta[((size_t)b*NS + s)*C1];
    float4* po = (float4*)&d_phifull[((size_t)b*NS + s)*C1];
#pragma unroll
    for (int j = 0; j < 4; j++) {
        to[j] = make_float4(tanhf(t4[j].x), tanhf(t4[j].y), tanhf(t4[j].z), tanhf(t4[j].w));
        po[j] = make_float4(tanhf(p4[j].x), tanhf(p4[j].y), tanhf(p4[j].z), tanhf(p4[j].w));
    }
}

// ---------------- K1b: g (full-res) projection, no activation ----------------
__global__ void __launch_bounds__(128)
proj64_kernel(const float* __restrict__ x,
              const float* __restrict__ wg, const float* __restrict__ bg) {
    __shared__ float sw[CH*C2];  // [c][o]
    __shared__ float sb[C2];
    int tid = threadIdx.x;
    for (int i = tid; i < CH*C2; i += 128) {
        int o = i >> 7, c = i & 127;   // source [o][c], o<64
        sw[c*C2 + o] = wg[i];
    }
    if (tid < C2) sb[tid] = bg[tid];
    __syncthreads();

    int b = blockIdx.y;
    int s = blockIdx.x * 128 + tid;
    const float* xp = x + (size_t)b*CH*NS + s;

    float4 a[16];
#pragma unroll
    for (int j = 0; j < 16; j++)
        a[j] = make_float4(sb[4*j], sb[4*j+1], sb[4*j+2], sb[4*j+3]);

#pragma unroll 2
    for (int c = 0; c < CH; c++) {
        float xv = xp[(size_t)c*NS];
        const float4* w4 = (const float4*)(sw + c*C2);
#pragma unroll
        for (int j = 0; j < 16; j++) {
            float4 w = w4[j];
            a[j].x = fmaf(xv, w.x, a[j].x); a[j].y = fmaf(xv, w.y, a[j].y);
            a[j].z = fmaf(xv, w.z, a[j].z); a[j].w = fmaf(xv, w.w, a[j].w);
        }
    }
    float4* go = (float4*)&d_gfull[((size_t)b*NS + s)*C2];
#pragma unroll
    for (int j = 0; j < 16; j++) go[j] = a[j];
}

// ---------------- K2: 2x2 max-pool over (w,h) ----------------
__global__ void pool16_kernel() {
    int idx = blockIdx.x * 256 + threadIdx.x;       // over BS*MM*(C1/4)
    if (idx >= BS*MM*(C1/4)) return;
    int kq = idx & 3;
    int m  = (idx >> 2) & (MM - 1);
    int b  = idx >> 14;
    int n = m >> 8, wp = (m >> 4) & 15, hp = m & 15;
    int sbase = n*1024 + wp*64 + hp*2;
    const float4* src = (const float4*)d_phifull + (size_t)b*NS*(C1/4);
    float4 v0 = src[(size_t)(sbase     )*(C1/4) + kq];
    float4 v1 = src[(size_t)(sbase + 1 )*(C1/4) + kq];
    float4 v2 = src[(size_t)(sbase + 32)*(C1/4) + kq];
    float4 v3 = src[(size_t)(sbase + 33)*(C1/4) + kq];
    float4 r;
    r.x = fmaxf(fmaxf(v0.x, v1.x), fmaxf(v2.x, v3.x));
    r.y = fmaxf(fmaxf(v0.y, v1.y), fmaxf(v2.y, v3.y));
    r.z = fmaxf(fmaxf(v0.z, v1.z), fmaxf(v2.z, v3.z));
    r.w = fmaxf(fmaxf(v0.w, v1.w), fmaxf(v2.w, v3.w));
    ((float4*)d_phi)[idx] = r;
}

__global__ void pool64_kernel() {
    int idx = blockIdx.x * 256 + threadIdx.x;       // over BS*MM*(C2/4)
    if (idx >= BS*MM*(C2/4)) return;
    int kq = idx & 15;
    int m  = (idx >> 4) & (MM - 1);
    int b  = idx >> 16;
    int n = m >> 8, wp = (m >> 4) & 15, hp = m & 15;
    int sbase = n*1024 + wp*64 + hp*2;
    const float4* src = (const float4*)d_gfull + (size_t)b*NS*(C2/4);
    float4 v0 = src[(size_t)(sbase     )*(C2/4) + kq];
    float4 v1 = src[(size_t)(sbase + 1 )*(C2/4) + kq];
    float4 v2 = src[(size_t)(sbase + 32)*(C2/4) + kq];
    float4 v3 = src[(size_t)(sbase + 33)*(C2/4) + kq];
    float4 r;
    r.x = fmaxf(fmaxf(v0.x, v1.x), fmaxf(v2.x, v3.x));
    r.y = fmaxf(fmaxf(v0.y, v1.y), fmaxf(v2.y, v3.y));
    r.z = fmaxf(fmaxf(v0.z, v1.z), fmaxf(v2.z, v3.z));
    r.w = fmaxf(fmaxf(v0.w, v1.w), fmaxf(v2.w, v3.w));
    ((float4*)d_g)[idx] = r;
}

// ---------------- K3: column denominators  denom[m] = sum_n exp(theta_n . phi_m) ----
// Scores bounded in [-16,16] (tanh inputs, c1=16) -> no max subtraction needed.
__global__ void __launch_bounds__(256)
denom_kernel() {
    __shared__ float4 sth[256*4];   // 256 theta rows
    int tid = threadIdx.x;
    int b = blockIdx.z;
    int m = blockIdx.x * 256 + tid;
    const float4* pp = (const float4*)&d_phi[((size_t)b*MM + m)*C1];
    float4 p0 = pp[0], p1 = pp[1], p2 = pp[2], p3 = pp[3];
    float acc = 0.f;
    int n0 = blockIdx.y * (NS/NCHUNK);
    for (int t0 = n0; t0 < n0 + NS/NCHUNK; t0 += 256) {
        const float4* tp = (const float4*)&d_theta[((size_t)b*NS + t0 + tid)*C1];
#pragma unroll
        for (int j = 0; j < 4; j++) sth[tid*4 + j] = tp[j];
        __syncthreads();
#pragma unroll 4
        for (int nn = 0; nn < 256; nn++) {
            float4 t0v = sth[nn*4+0], t1v = sth[nn*4+1], t2v = sth[nn*4+2], t3v = sth[nn*4+3];
            acc += __expf(dot16(t0v, t1v, t2v, t3v, p0, p1, p2, p3));
        }
        __syncthreads();
    }
    d_denomp[((size_t)b*MM + m)*NCHUNK + blockIdx.y] = acc;
}

// ---------------- K5: attn_g[n,:] = sum_m exp(theta_n . phi_m) * (g[m,:]/denom[m]) ----
__global__ void __launch_bounds__(128)
attn_kernel() {
    __shared__ float4 sphi[128*4];   // 8 KB
    __shared__ float4 sg[128*16];    // 32 KB (g pre-divided by denom)
    int tid = threadIdx.x;
    int gid = blockIdx.x * 128 + tid;   // gid = b*NS + n
    int b = gid >> 14;
    const float4* tp = (const float4*)&d_theta[(size_t)gid*C1];
    float4 t0 = tp[0], t1 = tp[1], t2 = tp[2], t3 = tp[3];
    float4 acc[16];
#pragma unroll
    for (int j = 0; j < 16; j++) acc[j] = make_float4(0.f, 0.f, 0.f, 0.f);

    for (int mt = 0; mt < MM; mt += 128) {
        size_t mi = (size_t)b*MM + mt + tid;
        const float4* pp = (const float4*)&d_phi[mi*C1];
#pragma unroll
        for (int j = 0; j < 4; j++) sphi[tid*4 + j] = pp[j];
        float dsum = 0.f;
#pragma unroll
        for (int j = 0; j < NCHUNK; j++) dsum += d_denomp[mi*NCHUNK + j];
        float rd = 1.0f / dsum;
        const float4* gp = (const float4*)&d_g[mi*C2];
#pragma unroll
        for (int j = 0; j < 16; j++) {
            float4 v = gp[j];
            v.x *= rd; v.y *= rd; v.z *= rd; v.w *= rd;
            sg[tid*16 + j] = v;
        }
        __syncthreads();
#pragma unroll 2
        for (int mm = 0; mm < 128; mm++) {
            float4 p0 = sphi[mm*4+0], p1 = sphi[mm*4+1], p2 = sphi[mm*4+2], p3 = sphi[mm*4+3];
            float e = __expf(dot16(t0, t1, t2, t3, p0, p1, p2, p3));
            const float4* gr = &sg[mm*16];
#pragma unroll
            for (int j = 0; j < 16; j++) {
                float4 gv = gr[j];
                acc[j].x = fmaf(e, gv.x, acc[j].x);
                acc[j].y = fmaf(e, gv.y, acc[j].y);
                acc[j].z = fmaf(e, gv.z, acc[j].z);
                acc[j].w = fmaf(e, gv.w, acc[j].w);
            }
        }
        __syncthreads();
    }
    float4* op = (float4*)&d_attng[(size_t)gid*C2];
#pragma unroll
    for (int j = 0; j < 16; j++) op[j] = acc[j];
}

// ---------------- K6: final 64->128 conv + residual blend; write both outputs ----
__global__ void __launch_bounds__(128)
out_kernel(const float* __restrict__ x,
           const float* __restrict__ wag, const float* __restrict__ bag,
           const float* __restrict__ gamma, float* __restrict__ out) {
    __shared__ float sw[CH*C2];   // [o][c], direct copy (32 KB)
    __shared__ float sb[CH];
    int tid = threadIdx.x;
    for (int i = tid; i < CH*C2; i += 128) sw[i] = wag[i];
    sb[tid] = bag[tid];
    __syncthreads();

    float alpha = 1.0f / (1.0f + expf(-gamma[0]));
    int b = blockIdx.y;
    int s = blockIdx.x * 128 + tid;

    float4 a[16];
    const float4* ap = (const float4*)&d_attng[((size_t)b*NS + s)*C2];
#pragma unroll
    for (int j = 0; j < 16; j++) a[j] = ap[j];

    const float* xp = x + (size_t)b*CH*NS + s;
    float* o0 = out + (size_t)b*CH*NS + s;
    float* o1 = o0 + (size_t)BS*CH*NS;

#pragma unroll 2
    for (int o = 0; o < CH; o++) {
        const float4* w4 = (const float4*)(sw + o*C2);
        float y0 = sb[o], y1 = 0.f, y2 = 0.f, y3 = 0.f;
#pragma unroll
        for (int j = 0; j < 16; j += 4) {
            float4 w;
            w = w4[j+0]; y0 = fmaf(a[j+0].x, w.x, y0); y0 = fmaf(a[j+0].y, w.y, y0);
                         y0 = fmaf(a[j+0].z, w.z, y0); y0 = fmaf(a[j+0].w, w.w, y0);
            w = w4[j+1]; y1 = fmaf(a[j+1].x, w.x, y1); y1 = fmaf(a[j+1].y, w.y, y1);
                         y1 = fmaf(a[j+1].z, w.z, y1); y1 = fmaf(a[j+1].w, w.w, y1);
            w = w4[j+2]; y2 = fmaf(a[j+2].x, w.x, y2); y2 = fmaf(a[j+2].y, w.y, y2);
                         y2 = fmaf(a[j+2].z, w.z, y2); y2 = fmaf(a[j+2].w, w.w, y2);
            w = w4[j+3]; y3 = fmaf(a[j+3].x, w.x, y3); y3 = fmaf(a[j+3].y, w.y, y3);
                         y3 = fmaf(a[j+3].z, w.z, y3); y3 = fmaf(a[j+3].w, w.w, y3);
        }
        float y = (y0 + y1) + (y2 + y3);
        float xv = xp[(size_t)o*NS];
        o0[(size_t)o*NS] = (1.0f - alpha)*xv + alpha*y;
        o1[(size_t)o*NS] = y;
    }
}

// ---------------- launch ----------------
extern "C" void kernel_launch(void* const* d_in, const int* in_sizes, int n_in,
                              void* d_out, int out_size) {
    const float* x     = (const float*)d_in[0];
    const float* wth   = (const float*)d_in[1];
    const float* bth   = (const float*)d_in[2];
    const float* wph   = (const float*)d_in[3];
    const float* bph   = (const float*)d_in[4];
    const float* wg    = (const float*)d_in[5];
    const float* bg    = (const float*)d_in[6];
    const float* wag   = (const float*)d_in[7];
    const float* bag   = (const float*)d_in[8];
    const float* gamma = (const float*)d_in[9];
    float* out = (float*)d_out;

    proj16_kernel<<<dim3(NS/128, BS), 128>>>(x, wth, bth, wph, bph);
    proj64_kernel<<<dim3(NS/128, BS), 128>>>(x, wg, bg);
    pool16_kernel<<<(BS*MM*(C1/4) + 255)/256, 256>>>();
    pool64_kernel<<<(BS*MM*(C2/4) + 255)/256, 256>>>();
    denom_kernel<<<dim3(MM/256, NCHUNK, BS), 256>>>();
    attn_kernel<<<BS*NS/128, 128>>>();
    out_kernel<<<dim3(NS/128, BS), 128>>>(x, wag, bag, gamma, out);
}

// round 4
// speedup vs baseline: 3.2063x; 3.2063x over previous
#include <cuda_runtime.h>
#include <cuda_bf16.h>
#include <cstdint>
#include <math.h>

#define BS 2
#define CH 128
#define NS 16384
#define MM 4096
#define C1 16
#define C2 64
#define NCHUNK 8
#define LOG2E 1.4426950408889634f

// ---------------- scratch (device globals; no allocs allowed) ----------------
__device__ __align__(16) float    d_phifull[BS*NS*C1];  // tanh(phi) fp32, pre-pool
__device__ __align__(16) float    d_gfull  [BS*NS*C2];  // g proj fp32, pre-pool
__device__ __align__(16) uint32_t d_thB    [BS*NS*16];  // theta*log2e rows: [8 hi words][8 lo words]
__device__ __align__(16) uint32_t d_phB    [BS*MM*16];  // pooled phi rows, same layout
__device__ __align__(16) uint32_t d_gthi   [BS*64*64*32]; // ghat hi tiles: [b][mt][c][q] word=(m=2q,2q+1)
__device__ __align__(16) uint32_t d_gtlo   [BS*64*64*32]; // ghat lo tiles
__device__ float d_denomp[BS*MM*NCHUNK];
__device__ float d_rdenom[BS*MM];
__device__ __align__(16) float d_attng[BS*NS*C2];

// ---------------- helpers ----------------
__device__ __forceinline__ float ex2f(float x){ float r; asm("ex2.approx.f32 %0, %1;" : "=f"(r) : "f"(x)); return r; }
__device__ __forceinline__ uint32_t cvt_bf16x2(float lo, float hi){
    uint32_t r; asm("cvt.rn.bf16x2.f32 %0, %1, %2;" : "=r"(r) : "f"(hi), "f"(lo)); return r;
}
// pack v0(lo half),v1(hi half) into bf16x2 hi-word + residual lo-word
__device__ __forceinline__ void split2(float v0, float v1, uint32_t& whi, uint32_t& wlo){
    whi = cvt_bf16x2(v0, v1);
    float r0 = v0 - __uint_as_float(whi << 16);
    float r1 = v1 - __uint_as_float(whi & 0xFFFF0000u);
    wlo = cvt_bf16x2(r0, r1);
}
__device__ __forceinline__ void mma_bf16(float* d, const uint32_t* a, uint32_t b0, uint32_t b1){
    asm volatile("mma.sync.aligned.m16n8k16.row.col.f32.bf16.bf16.f32 "
        "{%0,%1,%2,%3}, {%4,%5,%6,%7}, {%8,%9}, {%0,%1,%2,%3};"
        : "+f"(d[0]), "+f"(d[1]), "+f"(d[2]), "+f"(d[3])
        : "r"(a[0]), "r"(a[1]), "r"(a[2]), "r"(a[3]), "r"(b0), "r"(b1));
}

// ---------------- K1a: theta & phi projections ----------------
__global__ void __launch_bounds__(128)
proj16_kernel(const float* __restrict__ x,
              const float* __restrict__ wth, const float* __restrict__ bth,
              const float* __restrict__ wph, const float* __restrict__ bph) {
    __shared__ float swt[CH*C1];
    __shared__ float swp[CH*C1];
    __shared__ float sbt[C1], sbp[C1];
    int tid = threadIdx.x;
    for (int i = tid; i < CH*C1; i += 128) {
        int o = i >> 7, c = i & 127;
        swt[c*C1 + o] = wth[i];
        swp[c*C1 + o] = wph[i];
    }
    if (tid < C1) { sbt[tid] = bth[tid]; sbp[tid] = bph[tid]; }
    __syncthreads();

    int b = blockIdx.y;
    int s = blockIdx.x * 128 + tid;
    const float* xp = x + (size_t)b*CH*NS + s;

    float4 t4[4], p4[4];
#pragma unroll
    for (int j = 0; j < 4; j++) {
        t4[j] = make_float4(sbt[4*j], sbt[4*j+1], sbt[4*j+2], sbt[4*j+3]);
        p4[j] = make_float4(sbp[4*j], sbp[4*j+1], sbp[4*j+2], sbp[4*j+3]);
    }
#pragma unroll 4
    for (int c = 0; c < CH; c++) {
        float xv = xp[(size_t)c*NS];
        const float4* wt4 = (const float4*)(swt + c*C1);
        const float4* wp4 = (const float4*)(swp + c*C1);
#pragma unroll
        for (int j = 0; j < 4; j++) {
            float4 w = wt4[j];
            t4[j].x = fmaf(xv, w.x, t4[j].x); t4[j].y = fmaf(xv, w.y, t4[j].y);
            t4[j].z = fmaf(xv, w.z, t4[j].z); t4[j].w = fmaf(xv, w.w, t4[j].w);
            float4 v = wp4[j];
            p4[j].x = fmaf(xv, v.x, p4[j].x); p4[j].y = fmaf(xv, v.y, p4[j].y);
            p4[j].z = fmaf(xv, v.z, p4[j].z); p4[j].w = fmaf(xv, v.w, p4[j].w);
        }
    }
    size_t row = (size_t)b*NS + s;
    float4* po = (float4*)&d_phifull[row*C1];
#pragma unroll
    for (int j = 0; j < 4; j++)
        po[j] = make_float4(tanhf(p4[j].x), tanhf(p4[j].y), tanhf(p4[j].z), tanhf(p4[j].w));
    float tv[16];
#pragma unroll
    for (int j = 0; j < 4; j++) {
        tv[4*j+0] = tanhf(t4[j].x)*LOG2E; tv[4*j+1] = tanhf(t4[j].y)*LOG2E;
        tv[4*j+2] = tanhf(t4[j].z)*LOG2E; tv[4*j+3] = tanhf(t4[j].w)*LOG2E;
    }
    uint32_t w[16];
#pragma unroll
    for (int k = 0; k < 8; k++) split2(tv[2*k], tv[2*k+1], w[k], w[8+k]);
    uint4* dst = (uint4*)&d_thB[row*16];
    dst[0] = make_uint4(w[0],w[1],w[2],w[3]);
    dst[1] = make_uint4(w[4],w[5],w[6],w[7]);
    dst[2] = make_uint4(w[8],w[9],w[10],w[11]);
    dst[3] = make_uint4(w[12],w[13],w[14],w[15]);
}

// ---------------- K1b: g projection (fp32, pre-pool) ----------------
__global__ void __launch_bounds__(128)
proj64_kernel(const float* __restrict__ x,
              const float* __restrict__ wg, const float* __restrict__ bg) {
    __shared__ float sw[CH*C2];
    __shared__ float sb[C2];
    int tid = threadIdx.x;
    for (int i = tid; i < CH*C2; i += 128) {
        int o = i >> 7, c = i & 127;
        sw[c*C2 + o] = wg[i];
    }
    if (tid < C2) sb[tid] = bg[tid];
    __syncthreads();

    int b = blockIdx.y;
    int s = blockIdx.x * 128 + tid;
    const float* xp = x + (size_t)b*CH*NS + s;

    float4 a[16];
#pragma unroll
    for (int j = 0; j < 16; j++)
        a[j] = make_float4(sb[4*j], sb[4*j+1], sb[4*j+2], sb[4*j+3]);
#pragma unroll 2
    for (int c = 0; c < CH; c++) {
        float xv = xp[(size_t)c*NS];
        const float4* w4 = (const float4*)(sw + c*C2);
#pragma unroll
        for (int j = 0; j < 16; j++) {
            float4 w = w4[j];
            a[j].x = fmaf(xv, w.x, a[j].x); a[j].y = fmaf(xv, w.y, a[j].y);
            a[j].z = fmaf(xv, w.z, a[j].z); a[j].w = fmaf(xv, w.w, a[j].w);
        }
    }
    float4* go = (float4*)&d_gfull[((size_t)b*NS + s)*C2];
#pragma unroll
    for (int j = 0; j < 16; j++) go[j] = a[j];
}

// ---------------- K2a: pool phi -> split hi/lo rows ----------------
__global__ void pool16_kernel() {
    int idx = blockIdx.x * 128 + threadIdx.x;     // BS*MM
    if (idx >= BS*MM) return;
    int b = idx >> 12, m = idx & (MM-1);
    int n = m >> 8, wp = (m >> 4) & 15, hp = m & 15;
    int sbase = n*1024 + wp*64 + hp*2;
    const float4* src = (const float4*)d_phifull + ((size_t)b*NS)*4;
    float v[16];
#pragma unroll
    for (int q = 0; q < 4; q++) {
        float4 v0 = src[(size_t)(sbase     )*4 + q];
        float4 v1 = src[(size_t)(sbase + 1 )*4 + q];
        float4 v2 = src[(size_t)(sbase + 32)*4 + q];
        float4 v3 = src[(size_t)(sbase + 33)*4 + q];
        v[4*q+0] = fmaxf(fmaxf(v0.x, v1.x), fmaxf(v2.x, v3.x));
        v[4*q+1] = fmaxf(fmaxf(v0.y, v1.y), fmaxf(v2.y, v3.y));
        v[4*q+2] = fmaxf(fmaxf(v0.z, v1.z), fmaxf(v2.z, v3.z));
        v[4*q+3] = fmaxf(fmaxf(v0.w, v1.w), fmaxf(v2.w, v3.w));
    }
    uint32_t w[16];
#pragma unroll
    for (int k = 0; k < 8; k++) split2(v[2*k], v[2*k+1], w[k], w[8+k]);
    uint4* dst = (uint4*)&d_phB[(size_t)idx*16];
    dst[0] = make_uint4(w[0],w[1],w[2],w[3]);
    dst[1] = make_uint4(w[4],w[5],w[6],w[7]);
    dst[2] = make_uint4(w[8],w[9],w[10],w[11]);
    dst[3] = make_uint4(w[12],w[13],w[14],w[15]);
}

// ---------------- K3: denominators via warp MMA (S' = phi . theta^T) ----------
__global__ void __launch_bounds__(128)
denom_mma_kernel() {
    __shared__ uint32_t sth[128*20];   // 128 theta rows, pad stride 20
    int tid = threadIdx.x, wid = tid >> 5, lane = tid & 31;
    int gid = lane >> 2, tig = lane & 3;
    int b = blockIdx.z, mt = blockIdx.x, chunk = blockIdx.y;

    int m0 = mt*64 + wid*16;
    const uint32_t* ph = d_phB + (size_t)(b*MM + m0)*16;
    uint32_t pa_h[4], pa_l[4];
    pa_h[0] = ph[gid*16 + tig];       pa_h[1] = ph[(gid+8)*16 + tig];
    pa_h[2] = ph[gid*16 + tig+4];     pa_h[3] = ph[(gid+8)*16 + tig+4];
    pa_l[0] = ph[gid*16 + 8+tig];     pa_l[1] = ph[(gid+8)*16 + 8+tig];
    pa_l[2] = ph[gid*16 + 12+tig];    pa_l[3] = ph[(gid+8)*16 + 12+tig];

    float acc0 = 0.f, acc1 = 0.f;
    int nbase = chunk*(NS/NCHUNK);
    for (int st = 0; st < (NS/NCHUNK)/128; st++) {
        __syncthreads();
        {
            const uint4* src = (const uint4*)(d_thB + (size_t)(b*NS + nbase + st*128)*16);
            uint4 v0 = src[tid*4+0], v1 = src[tid*4+1], v2 = src[tid*4+2], v3 = src[tid*4+3];
            uint32_t* d = &sth[tid*20];
            d[0]=v0.x; d[1]=v0.y; d[2]=v0.z; d[3]=v0.w;
            d[4]=v1.x; d[5]=v1.y; d[6]=v1.z; d[7]=v1.w;
            d[8]=v2.x; d[9]=v2.y; d[10]=v2.z; d[11]=v2.w;
            d[12]=v3.x; d[13]=v3.y; d[14]=v3.z; d[15]=v3.w;
        }
        __syncthreads();
#pragma unroll 4
        for (int s8 = 0; s8 < 16; s8++) {
            int r = (s8*8 + gid)*20;
            uint32_t bh0 = sth[r + tig],   bh1 = sth[r + tig+4];
            uint32_t bl0 = sth[r + 8+tig], bl1 = sth[r + 12+tig];
            float d4[4] = {0.f, 0.f, 0.f, 0.f};
            mma_bf16(d4, pa_h, bh0, bh1);
            mma_bf16(d4, pa_h, bl0, bl1);
            mma_bf16(d4, pa_l, bh0, bh1);
            acc0 += ex2f(d4[0]) + ex2f(d4[1]);
            acc1 += ex2f(d4[2]) + ex2f(d4[3]);
        }
    }
    acc0 += __shfl_xor_sync(~0u, acc0, 1); acc0 += __shfl_xor_sync(~0u, acc0, 2);
    acc1 += __shfl_xor_sync(~0u, acc1, 1); acc1 += __shfl_xor_sync(~0u, acc1, 2);
    if (tig == 0) {
        d_denomp[(size_t)(b*MM + m0 + gid)*NCHUNK + chunk]     = acc0;
        d_denomp[(size_t)(b*MM + m0 + gid + 8)*NCHUNK + chunk] = acc1;
    }
}

// ---------------- K4: reciprocal denominators ----------------
__global__ void rdenom_kernel() {
    int i = blockIdx.x * 256 + threadIdx.x;
    if (i >= BS*MM) return;
    const float* p = &d_denomp[(size_t)i*NCHUNK];
    float s = 0.f;
#pragma unroll
    for (int j = 0; j < NCHUNK; j++) s += p[j];
    d_rdenom[i] = 1.0f / s;
}

// ---------------- K5: pool g, fold rdenom, split hi/lo, fragment layout ------
__global__ void pool64_kernel() {
    int idx = blockIdx.x * 256 + threadIdx.x;    // BS*MM*C2
    if (idx >= BS*MM*C2) return;
    int mloc = idx & 63;
    int c    = (idx >> 6) & 63;
    int mt   = (idx >> 12) & 63;
    int b    = idx >> 18;
    int m = mt*64 + mloc;
    int n = m >> 8, wp = (m >> 4) & 15, hp = m & 15;
    int sbase = n*1024 + wp*64 + hp*2;
    const float* g = d_gfull + ((size_t)b*NS)*C2 + c;
    float v = fmaxf(fmaxf(g[(size_t)(sbase)*C2],    g[(size_t)(sbase+1)*C2]),
                    fmaxf(g[(size_t)(sbase+32)*C2], g[(size_t)(sbase+33)*C2]));
    v *= d_rdenom[b*MM + m];
    __nv_bfloat16 h = __float2bfloat16_rn(v);
    float l = v - __bfloat162float(h);
    size_t ei = (size_t)((b*64 + mt)*64 + c)*64 + mloc;   // bf16 element index
    ((__nv_bfloat16*)d_gthi)[ei] = h;
    ((__nv_bfloat16*)d_gtlo)[ei] = __float2bfloat16_rn(l);
}

// ---------------- K6: attention via warp MMA, fragment-recycled --------------
__global__ void __launch_bounds__(128, 2)
attn_mma_kernel() {
    __shared__ uint32_t sphi[64*20];  // phi tile, pad 20
    __shared__ uint32_t sgh[64*36];   // ghat hi tile, pad 36
    __shared__ uint32_t sgl[64*36];   // ghat lo tile
    int tid = threadIdx.x, wid = tid >> 5, lane = tid & 31;
    int gid = lane >> 2, tig = lane & 3;
    int b = blockIdx.y, nt = blockIdx.x;
    int n0 = nt*128 + wid*32;

    // theta A fragments (loop-invariant)
    const uint32_t* th = d_thB + (size_t)(b*NS + n0)*16;
    uint32_t tah[2][4], tal[2][4];
#pragma unroll
    for (int rt = 0; rt < 2; rt++) {
        int r0 = (rt*16 + gid)*16, r1 = (rt*16 + gid + 8)*16;
        tah[rt][0] = th[r0 + tig];     tah[rt][1] = th[r1 + tig];
        tah[rt][2] = th[r0 + tig+4];   tah[rt][3] = th[r1 + tig+4];
        tal[rt][0] = th[r0 + 8+tig];   tal[rt][1] = th[r1 + 8+tig];
        tal[rt][2] = th[r0 + 12+tig];  tal[rt][3] = th[r1 + 12+tig];
    }

    float acc[2][8][4];
#pragma unroll
    for (int rt = 0; rt < 2; rt++)
#pragma unroll
        for (int ct = 0; ct < 8; ct++)
#pragma unroll
            for (int j = 0; j < 4; j++) acc[rt][ct][j] = 0.f;

    for (int mt = 0; mt < 64; mt++) {
        __syncthreads();
        {   // stage phi (64 rows x 16 words)
            int row = tid >> 1, half = (tid & 1)*8;
            const uint4* sp = (const uint4*)(d_phB + (size_t)(b*MM + mt*64 + row)*16 + half);
            uint4 v0 = sp[0], v1 = sp[1];
            uint32_t* d = &sphi[row*20 + half];
            d[0]=v0.x; d[1]=v0.y; d[2]=v0.z; d[3]=v0.w;
            d[4]=v1.x; d[5]=v1.y; d[6]=v1.z; d[7]=v1.w;
        }
        {   // stage ghat hi/lo (64 c-rows x 32 words each)
            int c = tid >> 1, half = (tid & 1)*16;
            size_t base = (size_t)((b*64 + mt)*64 + c)*32 + half;
            const uint4* gh = (const uint4*)(d_gthi + base);
            const uint4* gl = (const uint4*)(d_gtlo + base);
            uint32_t* dh = &sgh[c*36 + half];
            uint32_t* dl = &sgl[c*36 + half];
#pragma unroll
            for (int j = 0; j < 4; j++) {
                uint4 a = gh[j];
                dh[4*j+0]=a.x; dh[4*j+1]=a.y; dh[4*j+2]=a.z; dh[4*j+3]=a.w;
                uint4 e = gl[j];
                dl[4*j+0]=e.x; dl[4*j+1]=e.y; dl[4*j+2]=e.z; dl[4*j+3]=e.w;
            }
        }
        __syncthreads();

#pragma unroll
        for (int k = 0; k < 4; k++) {
            uint32_t aeh[2][4], ael[2][4];
#pragma unroll
            for (int rt = 0; rt < 2; rt++) {
                float s0[4] = {0.f,0.f,0.f,0.f};
                float s1[4] = {0.f,0.f,0.f,0.f};
                {
                    int r = ((2*k)*8 + gid)*20;
                    uint32_t bh0 = sphi[r + tig],   bh1 = sphi[r + tig+4];
                    uint32_t bl0 = sphi[r + 8+tig], bl1 = sphi[r + 12+tig];
                    mma_bf16(s0, tah[rt], bh0, bh1);
                    mma_bf16(s0, tal[rt], bh0, bh1);
                    mma_bf16(s0, tah[rt], bl0, bl1);
                }
                {
                    int r = ((2*k+1)*8 + gid)*20;
                    uint32_t bh0 = sphi[r + tig],   bh1 = sphi[r + tig+4];
                    uint32_t bl0 = sphi[r + 8+tig], bl1 = sphi[r + 12+tig];
                    mma_bf16(s1, tah[rt], bh0, bh1);
                    mma_bf16(s1, tal[rt], bh0, bh1);
                    mma_bf16(s1, tah[rt], bl0, bl1);
                }
                float e00 = ex2f(s0[0]), e01 = ex2f(s0[1]), e02 = ex2f(s0[2]), e03 = ex2f(s0[3]);
                float e10 = ex2f(s1[0]), e11 = ex2f(s1[1]), e12 = ex2f(s1[2]), e13 = ex2f(s1[3]);
                split2(e00, e01, aeh[rt][0], ael[rt][0]);
                split2(e02, e03, aeh[rt][1], ael[rt][1]);
                split2(e10, e11, aeh[rt][2], ael[rt][2]);
                split2(e12, e13, aeh[rt][3], ael[rt][3]);
            }
#pragma unroll
            for (int ct2 = 0; ct2 < 8; ct2++) {
                int cbase = (ct2*8 + gid)*36 + 8*k;
                uint32_t bh0 = sgh[cbase + tig], bh1 = sgh[cbase + tig+4];
                uint32_t bl0 = sgl[cbase + tig], bl1 = sgl[cbase + tig+4];
#pragma unroll
                for (int rt = 0; rt < 2; rt++) {
                    mma_bf16(acc[rt][ct2], aeh[rt], bh0, bh1);
                    mma_bf16(acc[rt][ct2], ael[rt], bh0, bh1);
                    mma_bf16(acc[rt][ct2], aeh[rt], bl0, bl1);
                }
            }
        }
    }

    // write attn_g (pre final conv)
#pragma unroll
    for (int rt = 0; rt < 2; rt++) {
        int n = n0 + rt*16 + gid;
#pragma unroll
        for (int ct = 0; ct < 8; ct++) {
            int c = ct*8 + tig*2;
            *(float2*)&d_attng[(size_t)(b*NS + n)*C2 + c]     = make_float2(acc[rt][ct][0], acc[rt][ct][1]);
            *(float2*)&d_attng[(size_t)(b*NS + n + 8)*C2 + c] = make_float2(acc[rt][ct][2], acc[rt][ct][3]);
        }
    }
}

// ---------------- K7: final 64->128 conv + residual blend --------------------
__global__ void __launch_bounds__(128)
out_kernel(const float* __restrict__ x,
           const float* __restrict__ wag, const float* __restrict__ bag,
           const float* __restrict__ gamma, float* __restrict__ out) {
    __shared__ float sw[CH*C2];
    __shared__ float sb[CH];
    int tid = threadIdx.x;
    for (int i = tid; i < CH*C2; i += 128) sw[i] = wag[i];
    sb[tid] = bag[tid];
    __syncthreads();

    float alpha = 1.0f / (1.0f + expf(-gamma[0]));
    int b = blockIdx.y;
    int s = blockIdx.x * 128 + tid;

    float4 a[16];
    const float4* ap = (const float4*)&d_attng[((size_t)b*NS + s)*C2];
#pragma unroll
    for (int j = 0; j < 16; j++) a[j] = ap[j];

    const float* xp = x + (size_t)b*CH*NS + s;
    float* o0 = out + (size_t)b*CH*NS + s;
    float* o1 = o0 + (size_t)BS*CH*NS;

#pragma unroll 2
    for (int o = 0; o < CH; o++) {
        const float4* wr = (const float4*)(sw + o*C2);
        float y0 = sb[o], y1 = 0.f, y2 = 0.f, y3 = 0.f;
#pragma unroll
        for (int j = 0; j < 16; j += 4) {
            float4 w;
            w = wr[j+0]; y0 = fmaf(a[j+0].x, w.x, y0); y0 = fmaf(a[j+0].y, w.y, y0);
                         y0 = fmaf(a[j+0].z, w.z, y0); y0 = fmaf(a[j+0].w, w.w, y0);
            w = wr[j+1]; y1 = fmaf(a[j+1].x, w.x, y1); y1 = fmaf(a[j+1].y, w.y, y1);
                         y1 = fmaf(a[j+1].z, w.z, y1); y1 = fmaf(a[j+1].w, w.w, y1);
            w = wr[j+2]; y2 = fmaf(a[j+2].x, w.x, y2); y2 = fmaf(a[j+2].y, w.y, y2);
                         y2 = fmaf(a[j+2].z, w.z, y2); y2 = fmaf(a[j+2].w, w.w, y2);
            w = wr[j+3]; y3 = fmaf(a[j+3].x, w.x, y3); y3 = fmaf(a[j+3].y, w.y, y3);
                         y3 = fmaf(a[j+3].z, w.z, y3); y3 = fmaf(a[j+3].w, w.w, y3);
        }
        float y = (y0 + y1) + (y2 + y3);
        float xv = xp[(size_t)o*NS];
        o0[(size_t)o*NS] = (1.0f - alpha)*xv + alpha*y;
        o1[(size_t)o*NS] = y;
    }
}

// ---------------- launch ----------------
extern "C" void kernel_launch(void* const* d_in, const int* in_sizes, int n_in,
                              void* d_out, int out_size) {
    const float* x     = (const float*)d_in[0];
    const float* wth   = (const float*)d_in[1];
    const float* bth   = (const float*)d_in[2];
    const float* wph   = (const float*)d_in[3];
    const float* bph   = (const float*)d_in[4];
    const float* wg    = (const float*)d_in[5];
    const float* bg    = (const float*)d_in[6];
    const float* wag   = (const float*)d_in[7];
    const float* bag   = (const float*)d_in[8];
    const float* gamma = (const float*)d_in[9];
    float* out = (float*)d_out;

    proj16_kernel<<<dim3(NS/128, BS), 128>>>(x, wth, bth, wph, bph);
    proj64_kernel<<<dim3(NS/128, BS), 128>>>(x, wg, bg);
    pool16_kernel<<<(BS*MM + 127)/128, 128>>>();
    denom_mma_kernel<<<dim3(MM/64, NCHUNK, BS), 128>>>();
    rdenom_kernel<<<(BS*MM + 255)/256, 256>>>();
    pool64_kernel<<<(BS*MM*C2 + 255)/256, 256>>>();
    attn_mma_kernel<<<dim3(NS/128, BS), 128>>>();
    out_kernel<<<dim3(NS/128, BS), 128>>>(x, wag, bag, gamma, out);
}

// round 5
// speedup vs baseline: 3.7446x; 1.1679x over previous
#include <cuda_runtime.h>
#include <cuda_bf16.h>
#include <cstdint>
#include <math.h>

#define BS 2
#define CH 128
#define NS 16384
#define MM 4096
#define C1 16
#define C2 64
#define NCHUNK 8
#define LOG2E 1.4426950408889634f

// ---------------- scratch (device globals; no allocs allowed) ----------------
__device__ __align__(16) float    d_phifull[BS*NS*C1];  // tanh(phi) fp32, pre-pool
__device__ __align__(16) float    d_gfull  [BS*NS*C2];  // g proj fp32, pre-pool
__device__ __align__(16) uint32_t d_thB    [BS*NS*16];  // theta*log2e rows: [8 hi words][8 lo words]
__device__ __align__(16) uint32_t d_phB    [BS*MM*16];  // pooled phi rows, same layout
__device__ __align__(16) uint32_t d_gthi   [BS*64*64*32]; // ghat hi tiles: [b][mt][c] 32 words (m pairs)
__device__ float d_denomp[BS*MM*NCHUNK];
__device__ float d_rdenom[BS*MM];
__device__ __align__(16) float d_attng[BS*NS*C2];

// ---------------- helpers ----------------
__device__ __forceinline__ float ex2f(float x){ float r; asm("ex2.approx.f32 %0, %1;" : "=f"(r) : "f"(x)); return r; }
__device__ __forceinline__ uint32_t cvt_bf16x2(float lo, float hi){
    uint32_t r; asm("cvt.rn.bf16x2.f32 %0, %1, %2;" : "=r"(r) : "f"(hi), "f"(lo)); return r;
}
// pack v0(lo half),v1(hi half) into bf16x2 hi-word + residual lo-word
__device__ __forceinline__ void split2(float v0, float v1, uint32_t& whi, uint32_t& wlo){
    whi = cvt_bf16x2(v0, v1);
    float r0 = v0 - __uint_as_float(whi << 16);
    float r1 = v1 - __uint_as_float(whi & 0xFFFF0000u);
    wlo = cvt_bf16x2(r0, r1);
}
__device__ __forceinline__ void mma_bf16(float* d, const uint32_t* a, uint32_t b0, uint32_t b1){
    asm volatile("mma.sync.aligned.m16n8k16.row.col.f32.bf16.bf16.f32 "
        "{%0,%1,%2,%3}, {%4,%5,%6,%7}, {%8,%9}, {%0,%1,%2,%3};"
        : "+f"(d[0]), "+f"(d[1]), "+f"(d[2]), "+f"(d[3])
        : "r"(a[0]), "r"(a[1]), "r"(a[2]), "r"(a[3]), "r"(b0), "r"(b1));
}

// ---------------- K1a: theta & phi projections ----------------
__global__ void __launch_bounds__(128)
proj16_kernel(const float* __restrict__ x,
              const float* __restrict__ wth, const float* __restrict__ bth,
              const float* __restrict__ wph, const float* __restrict__ bph) {
    __shared__ float swt[CH*C1];
    __shared__ float swp[CH*C1];
    __shared__ float sbt[C1], sbp[C1];
    int tid = threadIdx.x;
    for (int i = tid; i < CH*C1; i += 128) {
        int o = i >> 7, c = i & 127;
        swt[c*C1 + o] = wth[i];
        swp[c*C1 + o] = wph[i];
    }
    if (tid < C1) { sbt[tid] = bth[tid]; sbp[tid] = bph[tid]; }
    __syncthreads();

    int b = blockIdx.y;
    int s = blockIdx.x * 128 + tid;
    const float* xp = x + (size_t)b*CH*NS + s;

    float4 t4[4], p4[4];
#pragma unroll
    for (int j = 0; j < 4; j++) {
        t4[j] = make_float4(sbt[4*j], sbt[4*j+1], sbt[4*j+2], sbt[4*j+3]);
        p4[j] = make_float4(sbp[4*j], sbp[4*j+1], sbp[4*j+2], sbp[4*j+3]);
    }
#pragma unroll 4
    for (int c = 0; c < CH; c++) {
        float xv = xp[(size_t)c*NS];
        const float4* wt4 = (const float4*)(swt + c*C1);
        const float4* wp4 = (const float4*)(swp + c*C1);
#pragma unroll
        for (int j = 0; j < 4; j++) {
            float4 w = wt4[j];
            t4[j].x = fmaf(xv, w.x, t4[j].x); t4[j].y = fmaf(xv, w.y, t4[j].y);
            t4[j].z = fmaf(xv, w.z, t4[j].z); t4[j].w = fmaf(xv, w.w, t4[j].w);
            float4 v = wp4[j];
            p4[j].x = fmaf(xv, v.x, p4[j].x); p4[j].y = fmaf(xv, v.y, p4[j].y);
            p4[j].z = fmaf(xv, v.z, p4[j].z); p4[j].w = fmaf(xv, v.w, p4[j].w);
        }
    }
    size_t row = (size_t)b*NS + s;
    float4* po = (float4*)&d_phifull[row*C1];
#pragma unroll
    for (int j = 0; j < 4; j++)
        po[j] = make_float4(tanhf(p4[j].x), tanhf(p4[j].y), tanhf(p4[j].z), tanhf(p4[j].w));
    float tv[16];
#pragma unroll
    for (int j = 0; j < 4; j++) {
        tv[4*j+0] = tanhf(t4[j].x)*LOG2E; tv[4*j+1] = tanhf(t4[j].y)*LOG2E;
        tv[4*j+2] = tanhf(t4[j].z)*LOG2E; tv[4*j+3] = tanhf(t4[j].w)*LOG2E;
    }
    uint32_t w[16];
#pragma unroll
    for (int k = 0; k < 8; k++) split2(tv[2*k], tv[2*k+1], w[k], w[8+k]);
    uint4* dst = (uint4*)&d_thB[row*16];
    dst[0] = make_uint4(w[0],w[1],w[2],w[3]);
    dst[1] = make_uint4(w[4],w[5],w[6],w[7]);
    dst[2] = make_uint4(w[8],w[9],w[10],w[11]);
    dst[3] = make_uint4(w[12],w[13],w[14],w[15]);
}

// ---------------- K1b: g projection (fp32, pre-pool) ----------------
__global__ void __launch_bounds__(128)
proj64_kernel(const float* __restrict__ x,
              const float* __restrict__ wg, const float* __restrict__ bg) {
    __shared__ float sw[CH*C2];
    __shared__ float sb[C2];
    int tid = threadIdx.x;
    for (int i = tid; i < CH*C2; i += 128) {
        int o = i >> 7, c = i & 127;
        sw[c*C2 + o] = wg[i];
    }
    if (tid < C2) sb[tid] = bg[tid];
    __syncthreads();

    int b = blockIdx.y;
    int s = blockIdx.x * 128 + tid;
    const float* xp = x + (size_t)b*CH*NS + s;

    float4 a[16];
#pragma unroll
    for (int j = 0; j < 16; j++)
        a[j] = make_float4(sb[4*j], sb[4*j+1], sb[4*j+2], sb[4*j+3]);
#pragma unroll 2
    for (int c = 0; c < CH; c++) {
        float xv = xp[(size_t)c*NS];
        const float4* w4 = (const float4*)(sw + c*C2);
#pragma unroll
        for (int j = 0; j < 16; j++) {
            float4 w = w4[j];
            a[j].x = fmaf(xv, w.x, a[j].x); a[j].y = fmaf(xv, w.y, a[j].y);
            a[j].z = fmaf(xv, w.z, a[j].z); a[j].w = fmaf(xv, w.w, a[j].w);
        }
    }
    float4* go = (float4*)&d_gfull[((size_t)b*NS + s)*C2];
#pragma unroll
    for (int j = 0; j < 16; j++) go[j] = a[j];
}

// ---------------- K2a: pool phi -> split hi/lo rows ----------------
__global__ void pool16_kernel() {
    int idx = blockIdx.x * 128 + threadIdx.x;     // BS*MM
    if (idx >= BS*MM) return;
    int b = idx >> 12, m = idx & (MM-1);
    int n = m >> 8, wp = (m >> 4) & 15, hp = m & 15;
    int sbase = n*1024 + wp*64 + hp*2;
    const float4* src = (const float4*)d_phifull + ((size_t)b*NS)*4;
    float v[16];
#pragma unroll
    for (int q = 0; q < 4; q++) {
        float4 v0 = src[(size_t)(sbase     )*4 + q];
        float4 v1 = src[(size_t)(sbase + 1 )*4 + q];
        float4 v2 = src[(size_t)(sbase + 32)*4 + q];
        float4 v3 = src[(size_t)(sbase + 33)*4 + q];
        v[4*q+0] = fmaxf(fmaxf(v0.x, v1.x), fmaxf(v2.x, v3.x));
        v[4*q+1] = fmaxf(fmaxf(v0.y, v1.y), fmaxf(v2.y, v3.y));
        v[4*q+2] = fmaxf(fmaxf(v0.z, v1.z), fmaxf(v2.z, v3.z));
        v[4*q+3] = fmaxf(fmaxf(v0.w, v1.w), fmaxf(v2.w, v3.w));
    }
    uint32_t w[16];
#pragma unroll
    for (int k = 0; k < 8; k++) split2(v[2*k], v[2*k+1], w[k], w[8+k]);
    uint4* dst = (uint4*)&d_phB[(size_t)idx*16];
    dst[0] = make_uint4(w[0],w[1],w[2],w[3]);
    dst[1] = make_uint4(w[4],w[5],w[6],w[7]);
    dst[2] = make_uint4(w[8],w[9],w[10],w[11]);
    dst[3] = make_uint4(w[12],w[13],w[14],w[15]);
}

// ---------------- K3: denominators via warp MMA (S' = phi . theta^T) ----------
__global__ void __launch_bounds__(128)
denom_mma_kernel() {
    __shared__ uint32_t sth[128*20];   // 128 theta rows, pad stride 20
    int tid = threadIdx.x, wid = tid >> 5, lane = tid & 31;
    int gid = lane >> 2, tig = lane & 3;
    int b = blockIdx.z, mt = blockIdx.x, chunk = blockIdx.y;

    int m0 = mt*64 + wid*16;
    const uint32_t* ph = d_phB + (size_t)(b*MM + m0)*16;
    uint32_t pa_h[4], pa_l[4];
    pa_h[0] = ph[gid*16 + tig];       pa_h[1] = ph[(gid+8)*16 + tig];
    pa_h[2] = ph[gid*16 + tig+4];     pa_h[3] = ph[(gid+8)*16 + tig+4];
    pa_l[0] = ph[gid*16 + 8+tig];     pa_l[1] = ph[(gid+8)*16 + 8+tig];
    pa_l[2] = ph[gid*16 + 12+tig];    pa_l[3] = ph[(gid+8)*16 + 12+tig];

    float acc0 = 0.f, acc1 = 0.f;
    int nbase = chunk*(NS/NCHUNK);
    for (int st = 0; st < (NS/NCHUNK)/128; st++) {
        __syncthreads();
        {
            const uint4* src = (const uint4*)(d_thB + (size_t)(b*NS + nbase + st*128)*16);
            uint4 v0 = src[tid*4+0], v1 = src[tid*4+1], v2 = src[tid*4+2], v3 = src[tid*4+3];
            uint32_t* d = &sth[tid*20];
            d[0]=v0.x; d[1]=v0.y; d[2]=v0.z; d[3]=v0.w;
            d[4]=v1.x; d[5]=v1.y; d[6]=v1.z; d[7]=v1.w;
            d[8]=v2.x; d[9]=v2.y; d[10]=v2.z; d[11]=v2.w;
            d[12]=v3.x; d[13]=v3.y; d[14]=v3.z; d[15]=v3.w;
        }
        __syncthreads();
#pragma unroll 4
        for (int s8 = 0; s8 < 16; s8++) {
            int r = (s8*8 + gid)*20;
            uint32_t bh0 = sth[r + tig],   bh1 = sth[r + tig+4];
            uint32_t bl0 = sth[r + 8+tig], bl1 = sth[r + 12+tig];
            float d4[4] = {0.f, 0.f, 0.f, 0.f};
            mma_bf16(d4, pa_h, bh0, bh1);
            mma_bf16(d4, pa_h, bl0, bl1);
            mma_bf16(d4, pa_l, bh0, bh1);
            acc0 += ex2f(d4[0]) + ex2f(d4[1]);
            acc1 += ex2f(d4[2]) + ex2f(d4[3]);
        }
    }
    acc0 += __shfl_xor_sync(~0u, acc0, 1); acc0 += __shfl_xor_sync(~0u, acc0, 2);
    acc1 += __shfl_xor_sync(~0u, acc1, 1); acc1 += __shfl_xor_sync(~0u, acc1, 2);
    if (tig == 0) {
        d_denomp[(size_t)(b*MM + m0 + gid)*NCHUNK + chunk]     = acc0;
        d_denomp[(size_t)(b*MM + m0 + gid + 8)*NCHUNK + chunk] = acc1;
    }
}

// ---------------- K4: reciprocal denominators ----------------
__global__ void rdenom_kernel() {
    int i = blockIdx.x * 256 + threadIdx.x;
    if (i >= BS*MM) return;
    const float* p = &d_denomp[(size_t)i*NCHUNK];
    float s = 0.f;
#pragma unroll
    for (int j = 0; j < NCHUNK; j++) s += p[j];
    d_rdenom[i] = 1.0f / s;
}

// ---------------- K5: pool g, fold rdenom, bf16 hi only, fragment layout -----
__global__ void pool64_kernel() {
    int idx = blockIdx.x * 256 + threadIdx.x;    // BS*MM*C2
    if (idx >= BS*MM*C2) return;
    int mloc = idx & 63;
    int c    = (idx >> 6) & 63;
    int mt   = (idx >> 12) & 63;
    int b    = idx >> 18;
    int m = mt*64 + mloc;
    int n = m >> 8, wp = (m >> 4) & 15, hp = m & 15;
    int sbase = n*1024 + wp*64 + hp*2;
    const float* g = d_gfull + ((size_t)b*NS)*C2 + c;
    float v = fmaxf(fmaxf(g[(size_t)(sbase)*C2],    g[(size_t)(sbase+1)*C2]),
                    fmaxf(g[(size_t)(sbase+32)*C2], g[(size_t)(sbase+33)*C2]));
    v *= d_rdenom[b*MM + m];
    size_t ei = (size_t)((b*64 + mt)*64 + c)*64 + mloc;   // bf16 element index
    ((__nv_bfloat16*)d_gthi)[ei] = __float2bfloat16_rn(v);
}

// ---------------- K6: attention via warp MMA, 8 warps x 16 rows --------------
__global__ void __launch_bounds__(256, 2)
attn_mma_kernel() {
    __shared__ uint32_t sphi[64*20];  // phi tile, pad 20 (5 KB)
    __shared__ uint32_t sgh[64*36];   // ghat hi tile, pad 36 (9 KB)
    int tid = threadIdx.x, wid = tid >> 5, lane = tid & 31;
    int gid = lane >> 2, tig = lane & 3;
    int b = blockIdx.y, nt = blockIdx.x;
    int n0 = nt*128 + wid*16;

    // theta A fragments (loop-invariant), 16 rows per warp
    const uint32_t* th = d_thB + (size_t)(b*NS + n0)*16;
    uint32_t tah[4], tal[4];
    {
        int r0 = gid*16, r1 = (gid + 8)*16;
        tah[0] = th[r0 + tig];     tah[1] = th[r1 + tig];
        tah[2] = th[r0 + tig+4];   tah[3] = th[r1 + tig+4];
        tal[0] = th[r0 + 8+tig];   tal[1] = th[r1 + 8+tig];
        tal[2] = th[r0 + 12+tig];  tal[3] = th[r1 + 12+tig];
    }

    float acc[8][4];
#pragma unroll
    for (int ct = 0; ct < 8; ct++)
#pragma unroll
        for (int j = 0; j < 4; j++) acc[ct][j] = 0.f;

    for (int mt = 0; mt < 64; mt++) {
        __syncthreads();
        {   // stage phi: 64 rows x 16 words; 256 threads x 1 uint4
            int row = tid >> 2, q = tid & 3;
            uint4 v = *(const uint4*)(d_phB + (size_t)(b*MM + mt*64 + row)*16 + q*4);
            uint32_t* d = &sphi[row*20 + q*4];
            d[0]=v.x; d[1]=v.y; d[2]=v.z; d[3]=v.w;
        }
        {   // stage ghat hi: 64 c-rows x 32 words; 256 threads x 2 uint4
            int c = tid >> 2, q = tid & 3;
            const uint4* gh = (const uint4*)(d_gthi + (size_t)((b*64 + mt)*64 + c)*32 + q*8);
            uint4 a0 = gh[0], a1 = gh[1];
            uint32_t* dh = &sgh[c*36 + q*8];
            dh[0]=a0.x; dh[1]=a0.y; dh[2]=a0.z; dh[3]=a0.w;
            dh[4]=a1.x; dh[5]=a1.y; dh[6]=a1.z; dh[7]=a1.w;
        }
        __syncthreads();

#pragma unroll
        for (int k = 0; k < 4; k++) {
            uint32_t aeh[4], ael[4];
            float s0[4] = {0.f,0.f,0.f,0.f};
            float s1[4] = {0.f,0.f,0.f,0.f};
            {
                int r = ((2*k)*8 + gid)*20;
                uint32_t bh0 = sphi[r + tig],   bh1 = sphi[r + tig+4];
                uint32_t bl0 = sphi[r + 8+tig], bl1 = sphi[r + 12+tig];
                mma_bf16(s0, tah, bh0, bh1);
                mma_bf16(s0, tal, bh0, bh1);
                mma_bf16(s0, tah, bl0, bl1);
            }
            {
                int r = ((2*k+1)*8 + gid)*20;
                uint32_t bh0 = sphi[r + tig],   bh1 = sphi[r + tig+4];
                uint32_t bl0 = sphi[r + 8+tig], bl1 = sphi[r + 12+tig];
                mma_bf16(s1, tah, bh0, bh1);
                mma_bf16(s1, tal, bh0, bh1);
                mma_bf16(s1, tah, bl0, bl1);
            }
            float e00 = ex2f(s0[0]), e01 = ex2f(s0[1]), e02 = ex2f(s0[2]), e03 = ex2f(s0[3]);
            float e10 = ex2f(s1[0]), e11 = ex2f(s1[1]), e12 = ex2f(s1[2]), e13 = ex2f(s1[3]);
            split2(e00, e01, aeh[0], ael[0]);
            split2(e02, e03, aeh[1], ael[1]);
            split2(e10, e11, aeh[2], ael[2]);
            split2(e12, e13, aeh[3], ael[3]);
#pragma unroll
            for (int ct = 0; ct < 8; ct++) {
                int cbase = (ct*8 + gid)*36 + 8*k;
                uint32_t bh0 = sgh[cbase + tig], bh1 = sgh[cbase + tig+4];
                mma_bf16(acc[ct], aeh, bh0, bh1);
                mma_bf16(acc[ct], ael, bh0, bh1);
            }
        }
    }

    // write attn_g (pre final conv)
    int n = n0 + gid;
#pragma unroll
    for (int ct = 0; ct < 8; ct++) {
        int c = ct*8 + tig*2;
        *(float2*)&d_attng[(size_t)(b*NS + n)*C2 + c]     = make_float2(acc[ct][0], acc[ct][1]);
        *(float2*)&d_attng[(size_t)(b*NS + n + 8)*C2 + c] = make_float2(acc[ct][2], acc[ct][3]);
    }
}

// ---------------- K7: final 64->128 conv + residual blend --------------------
__global__ void __launch_bounds__(128)
out_kernel(const float* __restrict__ x,
           const float* __restrict__ wag, const float* __restrict__ bag,
           const float* __restrict__ gamma, float* __restrict__ out) {
    __shared__ float sw[CH*C2];
    __shared__ float sb[CH];
    int tid = threadIdx.x;
    for (int i = tid; i < CH*C2; i += 128) sw[i] = wag[i];
    sb[tid] = bag[tid];
    __syncthreads();

    float alpha = 1.0f / (1.0f + expf(-gamma[0]));
    int b = blockIdx.y;
    int s = blockIdx.x * 128 + tid;

    float4 a[16];
    const float4* ap = (const float4*)&d_attng[((size_t)b*NS + s)*C2];
#pragma unroll
    for (int j = 0; j < 16; j++) a[j] = ap[j];

    const float* xp = x + (size_t)b*CH*NS + s;
    float* o0 = out + (size_t)b*CH*NS + s;
    float* o1 = o0 + (size_t)BS*CH*NS;

#pragma unroll 2
    for (int o = 0; o < CH; o++) {
        const float4* wr = (const float4*)(sw + o*C2);
        float y0 = sb[o], y1 = 0.f, y2 = 0.f, y3 = 0.f;
#pragma unroll
        for (int j = 0; j < 16; j += 4) {
            float4 w;
            w = wr[j+0]; y0 = fmaf(a[j+0].x, w.x, y0); y0 = fmaf(a[j+0].y, w.y, y0);
                         y0 = fmaf(a[j+0].z, w.z, y0); y0 = fmaf(a[j+0].w, w.w, y0);
            w = wr[j+1]; y1 = fmaf(a[j+1].x, w.x, y1); y1 = fmaf(a[j+1].y, w.y, y1);
                         y1 = fmaf(a[j+1].z, w.z, y1); y1 = fmaf(a[j+1].w, w.w, y1);
            w = wr[j+2]; y2 = fmaf(a[j+2].x, w.x, y2); y2 = fmaf(a[j+2].y, w.y, y2);
                         y2 = fmaf(a[j+2].z, w.z, y2); y2 = fmaf(a[j+2].w, w.w, y2);
            w = wr[j+3]; y3 = fmaf(a[j+3].x, w.x, y3); y3 = fmaf(a[j+3].y, w.y, y3);
                         y3 = fmaf(a[j+3].z, w.z, y3); y3 = fmaf(a[j+3].w, w.w, y3);
        }
        float y = (y0 + y1) + (y2 + y3);
        float xv = xp[(size_t)o*NS];
        o0[(size_t)o*NS] = (1.0f - alpha)*xv + alpha*y;
        o1[(size_t)o*NS] = y;
    }
}

// ---------------- launch ----------------
extern "C" void kernel_launch(void* const* d_in, const int* in_sizes, int n_in,
                              void* d_out, int out_size) {
    const float* x     = (const float*)d_in[0];
    const float* wth   = (const float*)d_in[1];
    const float* bth   = (const float*)d_in[2];
    const float* wph   = (const float*)d_in[3];
    const float* bph   = (const float*)d_in[4];
    const float* wg    = (const float*)d_in[5];
    const float* bg    = (const float*)d_in[6];
    const float* wag   = (const float*)d_in[7];
    const float* bag   = (const float*)d_in[8];
    const float* gamma = (const float*)d_in[9];
    float* out = (float*)d_out;

    proj16_kernel<<<dim3(NS/128, BS), 128>>>(x, wth, bth, wph, bph);
    proj64_kernel<<<dim3(NS/128, BS), 128>>>(x, wg, bg);
    pool16_kernel<<<(BS*MM + 127)/128, 128>>>();
    denom_mma_kernel<<<dim3(MM/64, NCHUNK, BS), 128>>>();
    rdenom_kernel<<<(BS*MM + 255)/256, 256>>>();
    pool64_kernel<<<(BS*MM*C2 + 255)/256, 256>>>();
    attn_mma_kernel<<<dim3(NS/128, BS), 256>>>();
    out_kernel<<<dim3(NS/128, BS), 128>>>(x, wag, bag, gamma, out);
}

// round 7
// speedup vs baseline: 3.7822x; 1.0100x over previous
#include <cuda_runtime.h>
#include <cuda_bf16.h>
#include <cstdint>
#include <math.h>

#define BS 2
#define CH 128
#define NS 16384
#define MM 4096
#define C1 16
#define C2 64
#define NCHUNK 8
#define LOG2E 1.4426950408889634f

// ---------------- scratch (device globals; no allocs allowed) ----------------
__device__ __align__(16) float    d_phifull[BS*NS*C1];  // tanh(phi) fp32, pre-pool
__device__ __align__(16) float    d_gfull  [BS*NS*C2];  // g proj fp32, pre-pool
__device__ __align__(16) uint32_t d_thB    [BS*NS*16];  // theta*log2e rows: [8 hi][8 lo] bf16x2 words
__device__ __align__(16) uint32_t d_phB    [BS*MM*16];  // pooled phi rows, same layout
__device__ __align__(16) uint32_t d_gthi   [BS*64*64*32]; // ghat hi tiles: [b][mt][c] 32 words (m pairs)
__device__ float d_denomp[BS*MM*NCHUNK];
__device__ float d_rdenom[BS*MM];
__device__ __align__(16) float d_attng[BS*NS*C2];

// ---------------- helpers ----------------
__device__ __forceinline__ float ex2f(float x){ float r; asm("ex2.approx.f32 %0, %1;" : "=f"(r) : "f"(x)); return r; }
__device__ __forceinline__ uint32_t cvt_bf16x2(float lo, float hi){
    uint32_t r; asm("cvt.rn.bf16x2.f32 %0, %1, %2;" : "=r"(r) : "f"(hi), "f"(lo)); return r;
}
__device__ __forceinline__ void split2(float v0, float v1, uint32_t& whi, uint32_t& wlo){
    whi = cvt_bf16x2(v0, v1);
    float r0 = v0 - __uint_as_float(whi << 16);
    float r1 = v1 - __uint_as_float(whi & 0xFFFF0000u);
    wlo = cvt_bf16x2(r0, r1);
}
__device__ __forceinline__ void mma_bf16(float* d, const uint32_t* a, uint32_t b0, uint32_t b1){
    asm volatile("mma.sync.aligned.m16n8k16.row.col.f32.bf16.bf16.f32 "
        "{%0,%1,%2,%3}, {%4,%5,%6,%7}, {%8,%9}, {%0,%1,%2,%3};"
        : "+f"(d[0]), "+f"(d[1]), "+f"(d[2]), "+f"(d[3])
        : "r"(a[0]), "r"(a[1]), "r"(a[2]), "r"(a[3]), "r"(b0), "r"(b1));
}
__device__ __forceinline__ void cp16(uint32_t saddr, const void* g){
    asm volatile("cp.async.cg.shared.global [%0], [%1], 16;" :: "r"(saddr), "l"(g));
}
__device__ __forceinline__ void cp_commit(){ asm volatile("cp.async.commit_group;" ::: "memory"); }
__device__ __forceinline__ void cp_wait0(){ asm volatile("cp.async.wait_group 0;" ::: "memory"); }
__device__ __forceinline__ void cp_wait1(){ asm volatile("cp.async.wait_group 1;" ::: "memory"); }

// ---------------- K1a: theta & phi projections ----------------
__global__ void __launch_bounds__(128)
proj16_kernel(const float* __restrict__ x,
              const float* __restrict__ wth, const float* __restrict__ bth,
              const float* __restrict__ wph, const float* __restrict__ bph) {
    __shared__ float swt[CH*C1];
    __shared__ float swp[CH*C1];
    __shared__ float sbt[C1], sbp[C1];
    int tid = threadIdx.x;
    for (int i = tid; i < CH*C1; i += 128) {
        int o = i >> 7, c = i & 127;
        swt[c*C1 + o] = wth[i];
        swp[c*C1 + o] = wph[i];
    }
    if (tid < C1) { sbt[tid] = bth[tid]; sbp[tid] = bph[tid]; }
    __syncthreads();

    int b = blockIdx.y;
    int s = blockIdx.x * 128 + tid;
    const float* xp = x + (size_t)b*CH*NS + s;

    float4 t4[4], p4[4];
#pragma unroll
    for (int j = 0; j < 4; j++) {
        t4[j] = make_float4(sbt[4*j], sbt[4*j+1], sbt[4*j+2], sbt[4*j+3]);
        p4[j] = make_float4(sbp[4*j], sbp[4*j+1], sbp[4*j+2], sbp[4*j+3]);
    }
#pragma unroll 4
    for (int c = 0; c < CH; c++) {
        float xv = xp[(size_t)c*NS];
        const float4* wt4 = (const float4*)(swt + c*C1);
        const float4* wp4 = (const float4*)(swp + c*C1);
#pragma unroll
        for (int j = 0; j < 4; j++) {
            float4 w = wt4[j];
            t4[j].x = fmaf(xv, w.x, t4[j].x); t4[j].y = fmaf(xv, w.y, t4[j].y);
            t4[j].z = fmaf(xv, w.z, t4[j].z); t4[j].w = fmaf(xv, w.w, t4[j].w);
            float4 v = wp4[j];
            p4[j].x = fmaf(xv, v.x, p4[j].x); p4[j].y = fmaf(xv, v.y, p4[j].y);
            p4[j].z = fmaf(xv, v.z, p4[j].z); p4[j].w = fmaf(xv, v.w, p4[j].w);
        }
    }
    size_t row = (size_t)b*NS + s;
    float4* po = (float4*)&d_phifull[row*C1];
#pragma unroll
    for (int j = 0; j < 4; j++)
        po[j] = make_float4(tanhf(p4[j].x), tanhf(p4[j].y), tanhf(p4[j].z), tanhf(p4[j].w));
    float tv[16];
#pragma unroll
    for (int j = 0; j < 4; j++) {
        tv[4*j+0] = tanhf(t4[j].x)*LOG2E; tv[4*j+1] = tanhf(t4[j].y)*LOG2E;
        tv[4*j+2] = tanhf(t4[j].z)*LOG2E; tv[4*j+3] = tanhf(t4[j].w)*LOG2E;
    }
    uint32_t w[16];
#pragma unroll
    for (int k = 0; k < 8; k++) split2(tv[2*k], tv[2*k+1], w[k], w[8+k]);
    uint4* dst = (uint4*)&d_thB[row*16];
    dst[0] = make_uint4(w[0],w[1],w[2],w[3]);
    dst[1] = make_uint4(w[4],w[5],w[6],w[7]);
    dst[2] = make_uint4(w[8],w[9],w[10],w[11]);
    dst[3] = make_uint4(w[12],w[13],w[14],w[15]);
}

// ---------------- K1b: g projection (fp32, pre-pool) ----------------
__global__ void __launch_bounds__(128)
proj64_kernel(const float* __restrict__ x,
              const float* __restrict__ wg, const float* __restrict__ bg) {
    __shared__ float sw[CH*C2];
    __shared__ float sb[C2];
    int tid = threadIdx.x;
    for (int i = tid; i < CH*C2; i += 128) {
        int o = i >> 7, c = i & 127;
        sw[c*C2 + o] = wg[i];
    }
    if (tid < C2) sb[tid] = bg[tid];
    __syncthreads();

    int b = blockIdx.y;
    int s = blockIdx.x * 128 + tid;
    const float* xp = x + (size_t)b*CH*NS + s;

    float4 a[16];
#pragma unroll
    for (int j = 0; j < 16; j++)
        a[j] = make_float4(sb[4*j], sb[4*j+1], sb[4*j+2], sb[4*j+3]);
#pragma unroll 2
    for (int c = 0; c < CH; c++) {
        float xv = xp[(size_t)c*NS];
        const float4* w4 = (const float4*)(sw + c*C2);
#pragma unroll
        for (int j = 0; j < 16; j++) {
            float4 w = w4[j];
            a[j].x = fmaf(xv, w.x, a[j].x); a[j].y = fmaf(xv, w.y, a[j].y);
            a[j].z = fmaf(xv, w.z, a[j].z); a[j].w = fmaf(xv, w.w, a[j].w);
        }
    }
    float4* go = (float4*)&d_gfull[((size_t)b*NS + s)*C2];
#pragma unroll
    for (int j = 0; j < 16; j++) go[j] = a[j];
}

// ---------------- K2a: pool phi -> split hi/lo rows ----------------
__global__ void pool16_kernel() {
    int idx = blockIdx.x * 128 + threadIdx.x;     // BS*MM
    if (idx >= BS*MM) return;
    int b = idx >> 12, m = idx & (MM-1);
    int n = m >> 8, wp = (m >> 4) & 15, hp = m & 15;
    int sbase = n*1024 + wp*64 + hp*2;
    const float4* src = (const float4*)d_phifull + ((size_t)b*NS)*4;
    float v[16];
#pragma unroll
    for (int q = 0; q < 4; q++) {
        float4 v0 = src[(size_t)(sbase     )*4 + q];
        float4 v1 = src[(size_t)(sbase + 1 )*4 + q];
        float4 v2 = src[(size_t)(sbase + 32)*4 + q];
        float4 v3 = src[(size_t)(sbase + 33)*4 + q];
        v[4*q+0] = fmaxf(fmaxf(v0.x, v1.x), fmaxf(v2.x, v3.x));
        v[4*q+1] = fmaxf(fmaxf(v0.y, v1.y), fmaxf(v2.y, v3.y));
        v[4*q+2] = fmaxf(fmaxf(v0.z, v1.z), fmaxf(v2.z, v3.z));
        v[4*q+3] = fmaxf(fmaxf(v0.w, v1.w), fmaxf(v2.w, v3.w));
    }
    uint32_t w[16];
#pragma unroll
    for (int k = 0; k < 8; k++) split2(v[2*k], v[2*k+1], w[k], w[8+k]);
    uint4* dst = (uint4*)&d_phB[(size_t)idx*16];
    dst[0] = make_uint4(w[0],w[1],w[2],w[3]);
    dst[1] = make_uint4(w[4],w[5],w[6],w[7]);
    dst[2] = make_uint4(w[8],w[9],w[10],w[11]);
    dst[3] = make_uint4(w[12],w[13],w[14],w[15]);
}

// ---------------- K3: denominators via warp MMA (S' = phi . theta^T) ----------
// 128 m per block (4 warps x 32 m = 2 fragment chains/warp); cp.async double-buffer
__global__ void __launch_bounds__(128)
denom_mma_kernel() {
    __shared__ uint32_t sth[2][128*20];   // 2 x 10 KB theta tiles, pad 20
    int tid = threadIdx.x, wid = tid >> 5, lane = tid & 31;
    int gid = lane >> 2, tig = lane & 3;
    int b = blockIdx.z, mt = blockIdx.x, chunk = blockIdx.y;

    int m0 = mt*128 + wid*32;
    uint32_t pa_h[2][4], pa_l[2][4];
#pragma unroll
    for (int sub = 0; sub < 2; sub++) {
        const uint32_t* ph = d_phB + (size_t)(b*MM + m0 + sub*16)*16;
        pa_h[sub][0] = ph[gid*16 + tig];       pa_h[sub][1] = ph[(gid+8)*16 + tig];
        pa_h[sub][2] = ph[gid*16 + tig+4];     pa_h[sub][3] = ph[(gid+8)*16 + tig+4];
        pa_l[sub][0] = ph[gid*16 + 8+tig];     pa_l[sub][1] = ph[(gid+8)*16 + 8+tig];
        pa_l[sub][2] = ph[gid*16 + 12+tig];    pa_l[sub][3] = ph[(gid+8)*16 + 12+tig];
    }

    int nbase = chunk*(NS/NCHUNK);
    // stage: thread tid loads row tid (4 x 16B)
    auto load_tile = [&](int st, int buf){
        const uint4* src = (const uint4*)(d_thB + (size_t)(b*NS + nbase + st*128 + tid)*16);
        uint32_t dst = (uint32_t)__cvta_generic_to_shared(&sth[buf][tid*20]);
#pragma unroll
        for (int q = 0; q < 4; q++) cp16(dst + q*16, src + q);
    };

    float acc[2][2] = {{0.f,0.f},{0.f,0.f}};
    load_tile(0, 0); cp_commit();
    const int NT = (NS/NCHUNK)/128;   // 16
    for (int st = 0; st < NT; st++) {
        int cur = st & 1;
        if (st + 1 < NT) { load_tile(st+1, cur^1); cp_commit(); cp_wait1(); }
        else cp_wait0();
        __syncthreads();
#pragma unroll 4
        for (int s8 = 0; s8 < 16; s8++) {
            int r = (s8*8 + gid)*20;
            uint32_t bh0 = sth[cur][r + tig],   bh1 = sth[cur][r + tig+4];
            uint32_t bl0 = sth[cur][r + 8+tig], bl1 = sth[cur][r + 12+tig];
            float d0[4] = {0.f,0.f,0.f,0.f};
            float d1[4] = {0.f,0.f,0.f,0.f};
            mma_bf16(d0, pa_h[0], bh0, bh1);
            mma_bf16(d1, pa_h[1], bh0, bh1);
            mma_bf16(d0, pa_h[0], bl0, bl1);
            mma_bf16(d1, pa_h[1], bl0, bl1);
            mma_bf16(d0, pa_l[0], bh0, bh1);
            mma_bf16(d1, pa_l[1], bh0, bh1);
            acc[0][0] += ex2f(d0[0]) + ex2f(d0[1]);
            acc[0][1] += ex2f(d0[2]) + ex2f(d0[3]);
            acc[1][0] += ex2f(d1[0]) + ex2f(d1[1]);
            acc[1][1] += ex2f(d1[2]) + ex2f(d1[3]);
        }
        __syncthreads();
    }
#pragma unroll
    for (int sub = 0; sub < 2; sub++) {
        float a0 = acc[sub][0], a1 = acc[sub][1];
        a0 += __shfl_xor_sync(~0u, a0, 1); a0 += __shfl_xor_sync(~0u, a0, 2);
        a1 += __shfl_xor_sync(~0u, a1, 1); a1 += __shfl_xor_sync(~0u, a1, 2);
        if (tig == 0) {
            d_denomp[(size_t)(b*MM + m0 + sub*16 + gid)*NCHUNK + chunk]     = a0;
            d_denomp[(size_t)(b*MM + m0 + sub*16 + gid + 8)*NCHUNK + chunk] = a1;
        }
    }
}

// ---------------- K4: reciprocal denominators ----------------
__global__ void rdenom_kernel() {
    int i = blockIdx.x * 256 + threadIdx.x;
    if (i >= BS*MM) return;
    const float* p = &d_denomp[(size_t)i*NCHUNK];
    float s = 0.f;
#pragma unroll
    for (int j = 0; j < NCHUNK; j++) s += p[j];
    d_rdenom[i] = 1.0f / s;
}

// ---------------- K5: pool g, fold rdenom, bf16 hi only, fragment layout -----
__global__ void pool64_kernel() {
    int idx = blockIdx.x * 256 + threadIdx.x;    // BS*MM*C2
    if (idx >= BS*MM*C2) return;
    int mloc = idx & 63;
    int c    = (idx >> 6) & 63;
    int mt   = (idx >> 12) & 63;
    int b    = idx >> 18;
    int m = mt*64 + mloc;
    int n = m >> 8, wp = (m >> 4) & 15, hp = m & 15;
    int sbase = n*1024 + wp*64 + hp*2;
    const float* g = d_gfull + ((size_t)b*NS)*C2 + c;
    float v = fmaxf(fmaxf(g[(size_t)(sbase)*C2],    g[(size_t)(sbase+1)*C2]),
                    fmaxf(g[(size_t)(sbase+32)*C2], g[(size_t)(sbase+33)*C2]));
    v *= d_rdenom[b*MM + m];
    size_t ei = (size_t)((b*64 + mt)*64 + c)*64 + mloc;
    ((__nv_bfloat16*)d_gthi)[ei] = __float2bfloat16_rn(v);
}

// ---------------- K6: attention via warp MMA, cp.async double-buffer ---------
__global__ void __launch_bounds__(256, 2)
attn_mma_kernel() {
    __shared__ uint32_t sphi[2][64*20];  // 2 x 5 KB
    __shared__ uint32_t sgh[2][64*36];   // 2 x 9 KB
    int tid = threadIdx.x, wid = tid >> 5, lane = tid & 31;
    int gid = lane >> 2, tig = lane & 3;
    int b = blockIdx.y, nt = blockIdx.x;
    int n0 = nt*128 + wid*16;

    // theta A fragments (loop-invariant), 16 rows per warp
    const uint32_t* th = d_thB + (size_t)(b*NS + n0)*16;
    uint32_t tah[4], tal[4];
    {
        int r0 = gid*16, r1 = (gid + 8)*16;
        tah[0] = th[r0 + tig];     tah[1] = th[r1 + tig];
        tah[2] = th[r0 + tig+4];   tah[3] = th[r1 + tig+4];
        tal[0] = th[r0 + 8+tig];   tal[1] = th[r1 + 8+tig];
        tal[2] = th[r0 + 12+tig];  tal[3] = th[r1 + 12+tig];
    }

    // stage: 256 threads; phi row=tid>>2 quad=tid&3 (1x16B); ghat c=tid>>2 (2x16B)
    auto load_tile = [&](int mt, int buf){
        int row = tid >> 2, q = tid & 3;
        uint32_t pd = (uint32_t)__cvta_generic_to_shared(&sphi[buf][row*20 + q*4]);
        cp16(pd, d_phB + (size_t)(b*MM + mt*64 + row)*16 + q*4);
        const uint32_t* gsrc = d_gthi + (size_t)((b*64 + mt)*64 + row)*32 + q*8;
        uint32_t gd = (uint32_t)__cvta_generic_to_shared(&sgh[buf][row*36 + q*8]);
        cp16(gd,      gsrc);
        cp16(gd + 16, gsrc + 4);
    };

    float acc[8][4];
#pragma unroll
    for (int ct = 0; ct < 8; ct++)
#pragma unroll
        for (int j = 0; j < 4; j++) acc[ct][j] = 0.f;

    load_tile(0, 0); cp_commit();
    for (int mt = 0; mt < 64; mt++) {
        int cur = mt & 1;
        if (mt + 1 < 64) { load_tile(mt+1, cur^1); cp_commit(); cp_wait1(); }
        else cp_wait0();
        __syncthreads();

#pragma unroll
        for (int k = 0; k < 4; k++) {
            uint32_t aeh[4], ael[4];
            float s0[4] = {0.f,0.f,0.f,0.f};
            float s1[4] = {0.f,0.f,0.f,0.f};
            {
                int r = ((2*k)*8 + gid)*20;
                uint32_t bh0 = sphi[cur][r + tig],   bh1 = sphi[cur][r + tig+4];
                uint32_t bl0 = sphi[cur][r + 8+tig], bl1 = sphi[cur][r + 12+tig];
                mma_bf16(s0, tah, bh0, bh1);
                mma_bf16(s0, tal, bh0, bh1);
                mma_bf16(s0, tah, bl0, bl1);
            }
            {
                int r = ((2*k+1)*8 + gid)*20;
                uint32_t bh0 = sphi[cur][r + tig],   bh1 = sphi[cur][r + tig+4];
                uint32_t bl0 = sphi[cur][r + 8+tig], bl1 = sphi[cur][r + 12+tig];
                mma_bf16(s1, tah, bh0, bh1);
                mma_bf16(s1, tal, bh0, bh1);
                mma_bf16(s1, tah, bl0, bl1);
            }
            float e00 = ex2f(s0[0]), e01 = ex2f(s0[1]), e02 = ex2f(s0[2]), e03 = ex2f(s0[3]);
            float e10 = ex2f(s1[0]), e11 = ex2f(s1[1]), e12 = ex2f(s1[2]), e13 = ex2f(s1[3]);
            split2(e00, e01, aeh[0], ael[0]);
            split2(e02, e03, aeh[1], ael[1]);
            split2(e10, e11, aeh[2], ael[2]);
            split2(e12, e13, aeh[3], ael[3]);
#pragma unroll
            for (int ct = 0; ct < 8; ct++) {
                int cbase = (ct*8 + gid)*36 + 8*k;
                uint32_t bh0 = sgh[cur][cbase + tig], bh1 = sgh[cur][cbase + tig+4];
                mma_bf16(acc[ct], aeh, bh0, bh1);
                mma_bf16(acc[ct], ael, bh0, bh1);
            }
        }
        __syncthreads();
    }

    // write attn_g (pre final conv)
    int n = n0 + gid;
#pragma unroll
    for (int ct = 0; ct < 8; ct++) {
        int c = ct*8 + tig*2;
        *(float2*)&d_attng[(size_t)(b*NS + n)*C2 + c]     = make_float2(acc[ct][0], acc[ct][1]);
        *(float2*)&d_attng[(size_t)(b*NS + n + 8)*C2 + c] = make_float2(acc[ct][2], acc[ct][3]);
    }
}

// ---------------- K7: final 64->128 conv + residual blend --------------------
__global__ void __launch_bounds__(128)
out_kernel(const float* __restrict__ x,
           const float* __restrict__ wag, const float* __restrict__ bag,
           const float* __restrict__ gamma, float* __restrict__ out) {
    __shared__ float sw[CH*C2];
    __shared__ float sb[CH];
    int tid = threadIdx.x;
    for (int i = tid; i < CH*C2; i += 128) sw[i] = wag[i];
    sb[tid] = bag[tid];
    __syncthreads();

    float alpha = 1.0f / (1.0f + expf(-gamma[0]));
    int b = blockIdx.y;
    int s = blockIdx.x * 128 + tid;

    float4 a[16];
    const float4* ap = (const float4*)&d_attng[((size_t)b*NS + s)*C2];
#pragma unroll
    for (int j = 0; j < 16; j++) a[j] = ap[j];

    const float* xp = x + (size_t)b*CH*NS + s;
    float* o0 = out + (size_t)b*CH*NS + s;
    float* o1 = o0 + (size_t)BS*CH*NS;

#pragma unroll 2
    for (int o = 0; o < CH; o++) {
        const float4* wr = (const float4*)(sw + o*C2);
        float y0 = sb[o], y1 = 0.f, y2 = 0.f, y3 = 0.f;
#pragma unroll
        for (int j = 0; j < 16; j += 4) {
            float4 w;
            w = wr[j+0]; y0 = fmaf(a[j+0].x, w.x, y0); y0 = fmaf(a[j+0].y, w.y, y0);
                         y0 = fmaf(a[j+0].z, w.z, y0); y0 = fmaf(a[j+0].w, w.w, y0);
            w = wr[j+1]; y1 = fmaf(a[j+1].x, w.x, y1); y1 = fmaf(a[j+1].y, w.y, y1);
                         y1 = fmaf(a[j+1].z, w.z, y1); y1 = fmaf(a[j+1].w, w.w, y1);
            w = wr[j+2]; y2 = fmaf(a[j+2].x, w.x, y2); y2 = fmaf(a[j+2].y, w.y, y2);
                         y2 = fmaf(a[j+2].z, w.z, y2); y2 = fmaf(a[j+2].w, w.w, y2);
            w = wr[j+3]; y3 = fmaf(a[j+3].x, w.x, y3); y3 = fmaf(a[j+3].y, w.y, y3);
                         y3 = fmaf(a[j+3].z, w.z, y3); y3 = fmaf(a[j+3].w, w.w, y3);
        }
        float y = (y0 + y1) + (y2 + y3);
        float xv = xp[(size_t)o*NS];
        o0[(size_t)o*NS] = (1.0f - alpha)*xv + alpha*y;
        o1[(size_t)o*NS] = y;
    }
}

// ---------------- launch ----------------
extern "C" void kernel_launch(void* const* d_in, const int* in_sizes, int n_in,
                              void* d_out, int out_size) {
    const float* x     = (const float*)d_in[0];
    const float* wth   = (const float*)d_in[1];
    const float* bth   = (const float*)d_in[2];
    const float* wph   = (const float*)d_in[3];
    const float* bph   = (const float*)d_in[4];
    const float* wg    = (const float*)d_in[5];
    const float* bg    = (const float*)d_in[6];
    const float* wag   = (const float*)d_in[7];
    const float* bag   = (const float*)d_in[8];
    const float* gamma = (const float*)d_in[9];
    float* out = (float*)d_out;

    proj16_kernel<<<dim3(NS/128, BS), 128>>>(x, wth, bth, wph, bph);
    proj64_kernel<<<dim3(NS/128, BS), 128>>>(x, wg, bg);
    pool16_kernel<<<(BS*MM + 127)/128, 128>>>();
    denom_mma_kernel<<<dim3(MM/128, NCHUNK, BS), 128>>>();
    rdenom_kernel<<<(BS*MM + 255)/256, 256>>>();
    pool64_kernel<<<(BS*MM*C2 + 255)/256, 256>>>();
    attn_mma_kernel<<<dim3(NS/128, BS), 256>>>();
    out_kernel<<<dim3(NS/128, BS), 128>>>(x, wag, bag, gamma, out);
}

// round 8
// speedup vs baseline: 4.2716x; 1.1294x over previous
#include <cuda_runtime.h>
#include <cuda_bf16.h>
#include <cstdint>
#include <math.h>

#define BS 2
#define CH 128
#define NS 16384
#define MM 4096
#define C1 16
#define C2 64
#define NCHUNK 16
#define LOG2E 1.4426950408889634f

// ---------------- scratch (device globals; no allocs allowed) ----------------
__device__ __align__(16) float    d_phifull[BS*NS*C1];  // tanh(phi) fp32, pre-pool
__device__ __align__(16) float    d_gfull  [BS*NS*C2];  // g proj fp32, pre-pool
__device__ __align__(16) uint32_t d_thB    [BS*NS*16];  // theta*log2e rows: [8 hi][8 lo] bf16x2 words
__device__ __align__(16) uint32_t d_phB    [BS*MM*16];  // pooled phi rows, same layout
__device__ __align__(16) uint32_t d_gthi   [BS*64*64*32]; // ghat hi tiles: [b][mt][c] 32 words (m pairs)
__device__ float d_denomp[BS*MM*NCHUNK];
__device__ float d_rdenom[BS*MM];
__device__ __align__(16) float d_attng[2*BS*NS*C2];     // two m-split partial buffers

// ---------------- helpers ----------------
__device__ __forceinline__ float ex2f(float x){ float r; asm("ex2.approx.f32 %0, %1;" : "=f"(r) : "f"(x)); return r; }
__device__ __forceinline__ uint32_t cvt_bf16x2(float lo, float hi){
    uint32_t r; asm("cvt.rn.bf16x2.f32 %0, %1, %2;" : "=r"(r) : "f"(hi), "f"(lo)); return r;
}
__device__ __forceinline__ void split2(float v0, float v1, uint32_t& whi, uint32_t& wlo){
    whi = cvt_bf16x2(v0, v1);
    float r0 = v0 - __uint_as_float(whi << 16);
    float r1 = v1 - __uint_as_float(whi & 0xFFFF0000u);
    wlo = cvt_bf16x2(r0, r1);
}
__device__ __forceinline__ void mma_bf16(float* d, const uint32_t* a, uint32_t b0, uint32_t b1){
    asm volatile("mma.sync.aligned.m16n8k16.row.col.f32.bf16.bf16.f32 "
        "{%0,%1,%2,%3}, {%4,%5,%6,%7}, {%8,%9}, {%0,%1,%2,%3};"
        : "+f"(d[0]), "+f"(d[1]), "+f"(d[2]), "+f"(d[3])
        : "r"(a[0]), "r"(a[1]), "r"(a[2]), "r"(a[3]), "r"(b0), "r"(b1));
}
__device__ __forceinline__ void cp16(uint32_t saddr, const void* g){
    asm volatile("cp.async.cg.shared.global [%0], [%1], 16;" :: "r"(saddr), "l"(g));
}
__device__ __forceinline__ void cp_commit(){ asm volatile("cp.async.commit_group;" ::: "memory"); }
__device__ __forceinline__ void cp_wait0(){ asm volatile("cp.async.wait_group 0;" ::: "memory"); }
__device__ __forceinline__ void cp_wait1(){ asm volatile("cp.async.wait_group 1;" ::: "memory"); }

// ---------------- K1a: theta & phi projections ----------------
__global__ void __launch_bounds__(128)
proj16_kernel(const float* __restrict__ x,
              const float* __restrict__ wth, const float* __restrict__ bth,
              const float* __restrict__ wph, const float* __restrict__ bph) {
    __shared__ float swt[CH*C1];
    __shared__ float swp[CH*C1];
    __shared__ float sbt[C1], sbp[C1];
    int tid = threadIdx.x;
    for (int i = tid; i < CH*C1; i += 128) {
        int o = i >> 7, c = i & 127;
        swt[c*C1 + o] = wth[i];
        swp[c*C1 + o] = wph[i];
    }
    if (tid < C1) { sbt[tid] = bth[tid]; sbp[tid] = bph[tid]; }
    __syncthreads();

    int b = blockIdx.y;
    int s = blockIdx.x * 128 + tid;
    const float* xp = x + (size_t)b*CH*NS + s;

    float4 t4[4], p4[4];
#pragma unroll
    for (int j = 0; j < 4; j++) {
        t4[j] = make_float4(sbt[4*j], sbt[4*j+1], sbt[4*j+2], sbt[4*j+3]);
        p4[j] = make_float4(sbp[4*j], sbp[4*j+1], sbp[4*j+2], sbp[4*j+3]);
    }
#pragma unroll 4
    for (int c = 0; c < CH; c++) {
        float xv = xp[(size_t)c*NS];
        const float4* wt4 = (const float4*)(swt + c*C1);
        const float4* wp4 = (const float4*)(swp + c*C1);
#pragma unroll
        for (int j = 0; j < 4; j++) {
            float4 w = wt4[j];
            t4[j].x = fmaf(xv, w.x, t4[j].x); t4[j].y = fmaf(xv, w.y, t4[j].y);
            t4[j].z = fmaf(xv, w.z, t4[j].z); t4[j].w = fmaf(xv, w.w, t4[j].w);
            float4 v = wp4[j];
            p4[j].x = fmaf(xv, v.x, p4[j].x); p4[j].y = fmaf(xv, v.y, p4[j].y);
            p4[j].z = fmaf(xv, v.z, p4[j].z); p4[j].w = fmaf(xv, v.w, p4[j].w);
        }
    }
    size_t row = (size_t)b*NS + s;
    float4* po = (float4*)&d_phifull[row*C1];
#pragma unroll
    for (int j = 0; j < 4; j++)
        po[j] = make_float4(tanhf(p4[j].x), tanhf(p4[j].y), tanhf(p4[j].z), tanhf(p4[j].w));
    float tv[16];
#pragma unroll
    for (int j = 0; j < 4; j++) {
        tv[4*j+0] = tanhf(t4[j].x)*LOG2E; tv[4*j+1] = tanhf(t4[j].y)*LOG2E;
        tv[4*j+2] = tanhf(t4[j].z)*LOG2E; tv[4*j+3] = tanhf(t4[j].w)*LOG2E;
    }
    uint32_t w[16];
#pragma unroll
    for (int k = 0; k < 8; k++) split2(tv[2*k], tv[2*k+1], w[k], w[8+k]);
    uint4* dst = (uint4*)&d_thB[row*16];
    dst[0] = make_uint4(w[0],w[1],w[2],w[3]);
    dst[1] = make_uint4(w[4],w[5],w[6],w[7]);
    dst[2] = make_uint4(w[8],w[9],w[10],w[11]);
    dst[3] = make_uint4(w[12],w[13],w[14],w[15]);
}

// ---------------- K1b: g projection (fp32, pre-pool) ----------------
__global__ void __launch_bounds__(128)
proj64_kernel(const float* __restrict__ x,
              const float* __restrict__ wg, const float* __restrict__ bg) {
    __shared__ float sw[CH*C2];
    __shared__ float sb[C2];
    int tid = threadIdx.x;
    for (int i = tid; i < CH*C2; i += 128) {
        int o = i >> 7, c = i & 127;
        sw[c*C2 + o] = wg[i];
    }
    if (tid < C2) sb[tid] = bg[tid];
    __syncthreads();

    int b = blockIdx.y;
    int s = blockIdx.x * 128 + tid;
    const float* xp = x + (size_t)b*CH*NS + s;

    float4 a[16];
#pragma unroll
    for (int j = 0; j < 16; j++)
        a[j] = make_float4(sb[4*j], sb[4*j+1], sb[4*j+2], sb[4*j+3]);
#pragma unroll 2
    for (int c = 0; c < CH; c++) {
        float xv = xp[(size_t)c*NS];
        const float4* w4 = (const float4*)(sw + c*C2);
#pragma unroll
        for (int j = 0; j < 16; j++) {
            float4 w = w4[j];
            a[j].x = fmaf(xv, w.x, a[j].x); a[j].y = fmaf(xv, w.y, a[j].y);
            a[j].z = fmaf(xv, w.z, a[j].z); a[j].w = fmaf(xv, w.w, a[j].w);
        }
    }
    float4* go = (float4*)&d_gfull[((size_t)b*NS + s)*C2];
#pragma unroll
    for (int j = 0; j < 16; j++) go[j] = a[j];
}

// ---------------- K2a: pool phi -> split hi/lo rows ----------------
__global__ void pool16_kernel() {
    int idx = blockIdx.x * 128 + threadIdx.x;     // BS*MM
    if (idx >= BS*MM) return;
    int b = idx >> 12, m = idx & (MM-1);
    int n = m >> 8, wp = (m >> 4) & 15, hp = m & 15;
    int sbase = n*1024 + wp*64 + hp*2;
    const float4* src = (const float4*)d_phifull + ((size_t)b*NS)*4;
    float v[16];
#pragma unroll
    for (int q = 0; q < 4; q++) {
        float4 v0 = src[(size_t)(sbase     )*4 + q];
        float4 v1 = src[(size_t)(sbase + 1 )*4 + q];
        float4 v2 = src[(size_t)(sbase + 32)*4 + q];
        float4 v3 = src[(size_t)(sbase + 33)*4 + q];
        v[4*q+0] = fmaxf(fmaxf(v0.x, v1.x), fmaxf(v2.x, v3.x));
        v[4*q+1] = fmaxf(fmaxf(v0.y, v1.y), fmaxf(v2.y, v3.y));
        v[4*q+2] = fmaxf(fmaxf(v0.z, v1.z), fmaxf(v2.z, v3.z));
        v[4*q+3] = fmaxf(fmaxf(v0.w, v1.w), fmaxf(v2.w, v3.w));
    }
    uint32_t w[16];
#pragma unroll
    for (int k = 0; k < 8; k++) split2(v[2*k], v[2*k+1], w[k], w[8+k]);
    uint4* dst = (uint4*)&d_phB[(size_t)idx*16];
    dst[0] = make_uint4(w[0],w[1],w[2],w[3]);
    dst[1] = make_uint4(w[4],w[5],w[6],w[7]);
    dst[2] = make_uint4(w[8],w[9],w[10],w[11]);
    dst[3] = make_uint4(w[12],w[13],w[14],w[15]);
}

// ---------------- K3: denominators via warp MMA (S' = phi . theta^T) ----------
// 128 m per block; NCHUNK=16 n-chunks for occupancy; cp.async double-buffer
__global__ void __launch_bounds__(128)
denom_mma_kernel() {
    __shared__ uint32_t sth[2][128*20];   // 2 x 10 KB theta tiles, pad 20
    int tid = threadIdx.x, wid = tid >> 5, lane = tid & 31;
    int gid = lane >> 2, tig = lane & 3;
    int b = blockIdx.z, mt = blockIdx.x, chunk = blockIdx.y;

    int m0 = mt*128 + wid*32;
    uint32_t pa_h[2][4], pa_l[2][4];
#pragma unroll
    for (int sub = 0; sub < 2; sub++) {
        const uint32_t* ph = d_phB + (size_t)(b*MM + m0 + sub*16)*16;
        pa_h[sub][0] = ph[gid*16 + tig];       pa_h[sub][1] = ph[(gid+8)*16 + tig];
        pa_h[sub][2] = ph[gid*16 + tig+4];     pa_h[sub][3] = ph[(gid+8)*16 + tig+4];
        pa_l[sub][0] = ph[gid*16 + 8+tig];     pa_l[sub][1] = ph[(gid+8)*16 + 8+tig];
        pa_l[sub][2] = ph[gid*16 + 12+tig];    pa_l[sub][3] = ph[(gid+8)*16 + 12+tig];
    }

    int nbase = chunk*(NS/NCHUNK);
    auto load_tile = [&](int st, int buf){
        const uint4* src = (const uint4*)(d_thB + (size_t)(b*NS + nbase + st*128 + tid)*16);
        uint32_t dst = (uint32_t)__cvta_generic_to_shared(&sth[buf][tid*20]);
#pragma unroll
        for (int q = 0; q < 4; q++) cp16(dst + q*16, src + q);
    };

    float acc[2][2] = {{0.f,0.f},{0.f,0.f}};
    load_tile(0, 0); cp_commit();
    const int NT = (NS/NCHUNK)/128;   // 8
    for (int st = 0; st < NT; st++) {
        int cur = st & 1;
        if (st + 1 < NT) { load_tile(st+1, cur^1); cp_commit(); cp_wait1(); }
        else cp_wait0();
        __syncthreads();
#pragma unroll 4
        for (int s8 = 0; s8 < 16; s8++) {
            int r = (s8*8 + gid)*20;
            uint32_t bh0 = sth[cur][r + tig],   bh1 = sth[cur][r + tig+4];
            uint32_t bl0 = sth[cur][r + 8+tig], bl1 = sth[cur][r + 12+tig];
            float d0[4] = {0.f,0.f,0.f,0.f};
            float d1[4] = {0.f,0.f,0.f,0.f};
            mma_bf16(d0, pa_h[0], bh0, bh1);
            mma_bf16(d1, pa_h[1], bh0, bh1);
            mma_bf16(d0, pa_h[0], bl0, bl1);
            mma_bf16(d1, pa_h[1], bl0, bl1);
            mma_bf16(d0, pa_l[0], bh0, bh1);
            mma_bf16(d1, pa_l[1], bh0, bh1);
            acc[0][0] += ex2f(d0[0]) + ex2f(d0[1]);
            acc[0][1] += ex2f(d0[2]) + ex2f(d0[3]);
            acc[1][0] += ex2f(d1[0]) + ex2f(d1[1]);
            acc[1][1] += ex2f(d1[2]) + ex2f(d1[3]);
        }
        __syncthreads();
    }
#pragma unroll
    for (int sub = 0; sub < 2; sub++) {
        float a0 = acc[sub][0], a1 = acc[sub][1];
        a0 += __shfl_xor_sync(~0u, a0, 1); a0 += __shfl_xor_sync(~0u, a0, 2);
        a1 += __shfl_xor_sync(~0u, a1, 1); a1 += __shfl_xor_sync(~0u, a1, 2);
        if (tig == 0) {
            d_denomp[(size_t)(b*MM + m0 + sub*16 + gid)*NCHUNK + chunk]     = a0;
            d_denomp[(size_t)(b*MM + m0 + sub*16 + gid + 8)*NCHUNK + chunk] = a1;
        }
    }
}

// ---------------- K4: reciprocal denominators ----------------
__global__ void rdenom_kernel() {
    int i = blockIdx.x * 256 + threadIdx.x;
    if (i >= BS*MM) return;
    const float* p = &d_denomp[(size_t)i*NCHUNK];
    float s = 0.f;
#pragma unroll
    for (int j = 0; j < NCHUNK; j++) s += p[j];
    d_rdenom[i] = 1.0f / s;
}

// ---------------- K5: pool g, fold rdenom, bf16 hi only, fragment layout -----
__global__ void pool64_kernel() {
    int idx = blockIdx.x * 256 + threadIdx.x;    // BS*MM*C2
    if (idx >= BS*MM*C2) return;
    int mloc = idx & 63;
    int c    = (idx >> 6) & 63;
    int mt   = (idx >> 12) & 63;
    int b    = idx >> 18;
    int m = mt*64 + mloc;
    int n = m >> 8, wp = (m >> 4) & 15, hp = m & 15;
    int sbase = n*1024 + wp*64 + hp*2;
    const float* g = d_gfull + ((size_t)b*NS)*C2 + c;
    float v = fmaxf(fmaxf(g[(size_t)(sbase)*C2],    g[(size_t)(sbase+1)*C2]),
                    fmaxf(g[(size_t)(sbase+32)*C2], g[(size_t)(sbase+33)*C2]));
    v *= d_rdenom[b*MM + m];
    size_t ei = (size_t)((b*64 + mt)*64 + c)*64 + mloc;
    ((__nv_bfloat16*)d_gthi)[ei] = __float2bfloat16_rn(v);
}

// ---------------- K6: attention via warp MMA; 2-way m-split; E hi-only MMA2 --
__global__ void __launch_bounds__(256, 2)
attn_mma_kernel() {
    __shared__ uint32_t sphi[2][64*20];  // 2 x 5 KB
    __shared__ uint32_t sgh[2][64*36];   // 2 x 9 KB
    int tid = threadIdx.x, wid = tid >> 5, lane = tid & 31;
    int gid = lane >> 2, tig = lane & 3;
    int b = blockIdx.y, nt = blockIdx.x, z = blockIdx.z;
    int n0 = nt*128 + wid*16;

    // theta A fragments (loop-invariant), 16 rows per warp
    const uint32_t* th = d_thB + (size_t)(b*NS + n0)*16;
    uint32_t tah[4], tal[4];
    {
        int r0 = gid*16, r1 = (gid + 8)*16;
        tah[0] = th[r0 + tig];     tah[1] = th[r1 + tig];
        tah[2] = th[r0 + tig+4];   tah[3] = th[r1 + tig+4];
        tal[0] = th[r0 + 8+tig];   tal[1] = th[r1 + 8+tig];
        tal[2] = th[r0 + 12+tig];  tal[3] = th[r1 + 12+tig];
    }

    auto load_tile = [&](int mt, int buf){
        int row = tid >> 2, q = tid & 3;
        uint32_t pd = (uint32_t)__cvta_generic_to_shared(&sphi[buf][row*20 + q*4]);
        cp16(pd, d_phB + (size_t)(b*MM + mt*64 + row)*16 + q*4);
        const uint32_t* gsrc = d_gthi + (size_t)((b*64 + mt)*64 + row)*32 + q*8;
        uint32_t gd = (uint32_t)__cvta_generic_to_shared(&sgh[buf][row*36 + q*8]);
        cp16(gd,      gsrc);
        cp16(gd + 16, gsrc + 4);
    };

    float acc[8][4];
#pragma unroll
    for (int ct = 0; ct < 8; ct++)
#pragma unroll
        for (int j = 0; j < 4; j++) acc[ct][j] = 0.f;

    int mt0 = z*32;
    load_tile(mt0, 0); cp_commit();
    for (int t = 0; t < 32; t++) {
        int cur = t & 1;
        if (t + 1 < 32) { load_tile(mt0 + t + 1, cur^1); cp_commit(); cp_wait1(); }
        else cp_wait0();
        __syncthreads();

#pragma unroll
        for (int k = 0; k < 4; k++) {
            uint32_t aeh[4];
            float s0[4] = {0.f,0.f,0.f,0.f};
            float s1[4] = {0.f,0.f,0.f,0.f};
            {
                int r = ((2*k)*8 + gid)*20;
                uint32_t bh0 = sphi[cur][r + tig],   bh1 = sphi[cur][r + tig+4];
                uint32_t bl0 = sphi[cur][r + 8+tig], bl1 = sphi[cur][r + 12+tig];
                mma_bf16(s0, tah, bh0, bh1);
                mma_bf16(s0, tal, bh0, bh1);
                mma_bf16(s0, tah, bl0, bl1);
            }
            {
                int r = ((2*k+1)*8 + gid)*20;
                uint32_t bh0 = sphi[cur][r + tig],   bh1 = sphi[cur][r + tig+4];
                uint32_t bl0 = sphi[cur][r + 8+tig], bl1 = sphi[cur][r + 12+tig];
                mma_bf16(s1, tah, bh0, bh1);
                mma_bf16(s1, tal, bh0, bh1);
                mma_bf16(s1, tah, bl0, bl1);
            }
            aeh[0] = cvt_bf16x2(ex2f(s0[0]), ex2f(s0[1]));
            aeh[1] = cvt_bf16x2(ex2f(s0[2]), ex2f(s0[3]));
            aeh[2] = cvt_bf16x2(ex2f(s1[0]), ex2f(s1[1]));
            aeh[3] = cvt_bf16x2(ex2f(s1[2]), ex2f(s1[3]));
#pragma unroll
            for (int ct = 0; ct < 8; ct++) {
                int cbase = (ct*8 + gid)*36 + 8*k;
                uint32_t bh0 = sgh[cur][cbase + tig], bh1 = sgh[cur][cbase + tig+4];
                mma_bf16(acc[ct], aeh, bh0, bh1);
            }
        }
        __syncthreads();
    }

    // write partial attn_g for this m-split
    float* outb = d_attng + (size_t)z*BS*NS*C2;
    int n = n0 + gid;
#pragma unroll
    for (int ct = 0; ct < 8; ct++) {
        int c = ct*8 + tig*2;
        *(float2*)&outb[(size_t)(b*NS + n)*C2 + c]     = make_float2(acc[ct][0], acc[ct][1]);
        *(float2*)&outb[(size_t)(b*NS + n + 8)*C2 + c] = make_float2(acc[ct][2], acc[ct][3]);
    }
}

// ---------------- K7: final 64->128 conv + residual blend --------------------
__global__ void __launch_bounds__(128)
out_kernel(const float* __restrict__ x,
           const float* __restrict__ wag, const float* __restrict__ bag,
           const float* __restrict__ gamma, float* __restrict__ out) {
    __shared__ float sw[CH*C2];
    __shared__ float sb[CH];
    int tid = threadIdx.x;
    for (int i = tid; i < CH*C2; i += 128) sw[i] = wag[i];
    sb[tid] = bag[tid];
    __syncthreads();

    float alpha = 1.0f / (1.0f + expf(-gamma[0]));
    int b = blockIdx.y;
    int s = blockIdx.x * 128 + tid;

    float4 a[16];
    const float4* ap0 = (const float4*)&d_attng[((size_t)b*NS + s)*C2];
    const float4* ap1 = (const float4*)&d_attng[(size_t)BS*NS*C2 + ((size_t)b*NS + s)*C2];
#pragma unroll
    for (int j = 0; j < 16; j++) {
        float4 u = ap0[j], v = ap1[j];
        a[j] = make_float4(u.x + v.x, u.y + v.y, u.z + v.z, u.w + v.w);
    }

    const float* xp = x + (size_t)b*CH*NS + s;
    float* o0 = out + (size_t)b*CH*NS + s;
    float* o1 = o0 + (size_t)BS*CH*NS;

#pragma unroll 2
    for (int o = 0; o < CH; o++) {
        const float4* wr = (const float4*)(sw + o*C2);
        float y0 = sb[o], y1 = 0.f, y2 = 0.f, y3 = 0.f;
#pragma unroll
        for (int j = 0; j < 16; j += 4) {
            float4 w;
            w = wr[j+0]; y0 = fmaf(a[j+0].x, w.x, y0); y0 = fmaf(a[j+0].y, w.y, y0);
                         y0 = fmaf(a[j+0].z, w.z, y0); y0 = fmaf(a[j+0].w, w.w, y0);
            w = wr[j+1]; y1 = fmaf(a[j+1].x, w.x, y1); y1 = fmaf(a[j+1].y, w.y, y1);
                         y1 = fmaf(a[j+1].z, w.z, y1); y1 = fmaf(a[j+1].w, w.w, y1);
            w = wr[j+2]; y2 = fmaf(a[j+2].x, w.x, y2); y2 = fmaf(a[j+2].y, w.y, y2);
                         y2 = fmaf(a[j+2].z, w.z, y2); y2 = fmaf(a[j+2].w, w.w, y2);
            w = wr[j+3]; y3 = fmaf(a[j+3].x, w.x, y3); y3 = fmaf(a[j+3].y, w.y, y3);
                         y3 = fmaf(a[j+3].z, w.z, y3); y3 = fmaf(a[j+3].w, w.w, y3);
        }
        float y = (y0 + y1) + (y2 + y3);
        float xv = xp[(size_t)o*NS];
        o0[(size_t)o*NS] = (1.0f - alpha)*xv + alpha*y;
        o1[(size_t)o*NS] = y;
    }
}

// ---------------- launch ----------------
extern "C" void kernel_launch(void* const* d_in, const int* in_sizes, int n_in,
                              void* d_out, int out_size) {
    const float* x     = (const float*)d_in[0];
    const float* wth   = (const float*)d_in[1];
    const float* bth   = (const float*)d_in[2];
    const float* wph   = (const float*)d_in[3];
    const float* bph   = (const float*)d_in[4];
    const float* wg    = (const float*)d_in[5];
    const float* bg    = (const float*)d_in[6];
    const float* wag   = (const float*)d_in[7];
    const float* bag   = (const float*)d_in[8];
    const float* gamma = (const float*)d_in[9];
    float* out = (float*)d_out;

    proj16_kernel<<<dim3(NS/128, BS), 128>>>(x, wth, bth, wph, bph);
    proj64_kernel<<<dim3(NS/128, BS), 128>>>(x, wg, bg);
    pool16_kernel<<<(BS*MM + 127)/128, 128>>>();
    denom_mma_kernel<<<dim3(MM/128, NCHUNK, BS), 128>>>();
    rdenom_kernel<<<(BS*MM + 255)/256, 256>>>();
    pool64_kernel<<<(BS*MM*C2 + 255)/256, 256>>>();
    attn_mma_kernel<<<dim3(NS/128, BS, 2), 256>>>();
    out_kernel<<<dim3(NS/128, BS), 128>>>(x, wag, bag, gamma, out);
}